// round 3
// baseline (speedup 1.0000x reference)
#include <cuda_runtime.h>
#include <cuda_fp16.h>

// Problem constants (fixed by dataset)
#define MAXN 50000
#define CDIM 64
#define SDIM 4
#define ODIM 64
#define KNEI 16

#define VT_BLOCKS 1184   // role-split: blocks [0, VT_BLOCKS) build the v-table
#define LG_BLOCKS 782    // blocks [VT_BLOCKS, VT_BLOCKS+LG_BLOCKS) build logits (ceil(50000/64))

// Scratch tables (static __device__ — allocation-free per harness rules)
// v-table fp16, interleaved layout: g_vh[j*128 + o2*4 + s] = half2 of outputs
// (2*o2, 2*o2+1) of matrix s  ->  one uint4 per lane covers all 4 s for 2 outputs.
__device__ __half2 g_vh[MAXN * 128];        // 25.6 MB — L2 resident
__device__ float   g_t[MAXN * SDIM];        // x[n]@Wt + bt
__device__ float   g_sl[MAXN * SDIM];       // src[j]@Ws + bs

// f32x2 packed FMA helpers
__device__ __forceinline__ unsigned long long fma2(unsigned long long a,
                                                   unsigned long long b,
                                                   unsigned long long c) {
    unsigned long long d;
    asm("fma.rn.f32x2 %0, %1, %2, %3;" : "=l"(d) : "l"(a), "l"(b), "l"(c));
    return d;
}
__device__ __forceinline__ unsigned long long pack2(float x, float y) {
    unsigned long long d;
    asm("mov.b64 %0, {%1, %2};" : "=l"(d) : "r"(__float_as_uint(x)), "r"(__float_as_uint(y)));
    return d;
}
__device__ __forceinline__ float hadd2(unsigned long long a) {
    unsigned int lo, hi;
    asm("mov.b64 {%0, %1}, %2;" : "=r"(lo), "=r"(hi) : "l"(a));
    return __uint_as_float(lo) + __uint_as_float(hi);
}

// ---------------------------------------------------------------------------
// Fused producer kernel: role-split grid.
//   blocks [0, VT_BLOCKS): v-table GEMM  v[j,s,o] = (src[j]@W_lin[s] + b)/4
//   blocks [VT_BLOCKS, +LG_BLOCKS): logits tables t[n,s], sl[n,s]
// ---------------------------------------------------------------------------
__global__ void __launch_bounds__(256) k_tables(const float* __restrict__ x,
                                                const float* __restrict__ src,
                                                const float* __restrict__ Wt,     // [64,4]
                                                const float* __restrict__ bt,     // [4]
                                                const float* __restrict__ Ws,     // [64,4]
                                                const float* __restrict__ bs,     // [4]
                                                const float* __restrict__ W_lin,  // [4,64,64]
                                                const float* __restrict__ b_lin,  // [4,64]
                                                int N)
{
    if (blockIdx.x < VT_BLOCKS) {
        // ------------------- v-table role -------------------
        // Two independent 128-thread half-blocks ("virtual blocks").
        int h  = threadIdx.x >> 7;      // 0/1
        int t  = threadIdx.x & 127;     // element id within row: t = o2*4 + s
        int o2 = t >> 2;                // output pair 0..31
        int s  = t & 3;                 // matrix id
        int oA = 2 * o2, oB = 2 * o2 + 1;

        // Weights packed by CHANNEL pairs for each of the 2 owned outputs:
        // wA[i] = (W[s][2i][oA], W[s][2i+1][oA])
        const float* Wb = W_lin + s * (CDIM * ODIM);
        unsigned long long wA[32], wB[32];
#pragma unroll
        for (int i = 0; i < 32; i++) {
            wA[i] = pack2(__ldg(Wb + (2 * i) * ODIM + oA), __ldg(Wb + (2 * i + 1) * ODIM + oA));
            wB[i] = pack2(__ldg(Wb + (2 * i) * ODIM + oB), __ldg(Wb + (2 * i + 1) * ODIM + oB));
        }
        float bA = __ldg(b_lin + s * ODIM + oA) * 0.25f;
        float bB = __ldg(b_lin + s * ODIM + oB) * 0.25f;

        int vb = blockIdx.x * 2 + h;            // virtual block id, 0..2*VT_BLOCKS-1
        for (int j0 = vb * 2; j0 < N; j0 += 4 * VT_BLOCKS) {
            int j1 = (j0 + 1 < N) ? j0 + 1 : j0;
            const ulonglong2* r0 = (const ulonglong2*)(src + j0 * CDIM);
            const ulonglong2* r1 = (const ulonglong2*)(src + j1 * CDIM);

            unsigned long long aA0 = 0, aB0 = 0, aA1 = 0, aB1 = 0;
#pragma unroll
            for (int i = 0; i < 16; i++) {
                ulonglong2 u0 = __ldg(r0 + i);   // channel pairs (4i,4i+1), (4i+2,4i+3)
                ulonglong2 u1 = __ldg(r1 + i);
                aA0 = fma2(wA[2 * i], u0.x, aA0);
                aB0 = fma2(wB[2 * i], u0.x, aB0);
                aA1 = fma2(wA[2 * i], u1.x, aA1);
                aB1 = fma2(wB[2 * i], u1.x, aB1);
                aA0 = fma2(wA[2 * i + 1], u0.y, aA0);
                aB0 = fma2(wB[2 * i + 1], u0.y, aB0);
                aA1 = fma2(wA[2 * i + 1], u1.y, aA1);
                aB1 = fma2(wB[2 * i + 1], u1.y, aB1);
            }
            float vA0 = fmaf(hadd2(aA0), 0.25f, bA);
            float vB0 = fmaf(hadd2(aB0), 0.25f, bB);
            g_vh[j0 * 128 + t] = __floats2half2_rn(vA0, vB0);
            if (j1 != j0) {
                float vA1 = fmaf(hadd2(aA1), 0.25f, bA);
                float vB1 = fmaf(hadd2(aB1), 0.25f, bB);
                g_vh[j1 * 128 + t] = __floats2half2_rn(vA1, vB1);
            }
        }
    } else {
        // ------------------- logits role -------------------
        __shared__ float xs[64][65];
        __shared__ float ss[64][65];
        __shared__ float wts[64][4];
        __shared__ float wss[64][4];

        int tid = threadIdx.x;
        int nb  = (blockIdx.x - VT_BLOCKS) * 64;

        wts[tid >> 2][tid & 3] = __ldg(Wt + tid);
        wss[tid >> 2][tid & 3] = __ldg(Ws + tid);

        for (int i = tid; i < 64 * 16; i += 256) {
            int row = i >> 4, c4 = i & 15;
            int node = nb + row;
            float4 xv = make_float4(0.f, 0.f, 0.f, 0.f);
            float4 sv = make_float4(0.f, 0.f, 0.f, 0.f);
            if (node < N) {
                xv = __ldg((const float4*)x + node * 16 + c4);
                sv = __ldg((const float4*)src + node * 16 + c4);
            }
            xs[row][c4 * 4 + 0] = xv.x; xs[row][c4 * 4 + 1] = xv.y;
            xs[row][c4 * 4 + 2] = xv.z; xs[row][c4 * 4 + 3] = xv.w;
            ss[row][c4 * 4 + 0] = sv.x; ss[row][c4 * 4 + 1] = sv.y;
            ss[row][c4 * 4 + 2] = sv.z; ss[row][c4 * 4 + 3] = sv.w;
        }
        __syncthreads();

        int node = tid >> 2;
        int s    = tid & 3;
        float at  = __ldg(bt + s);
        float as_ = __ldg(bs + s);
#pragma unroll
        for (int c = 0; c < CDIM; c++) {
            at  = fmaf(xs[node][c], wts[c][s], at);
            as_ = fmaf(ss[node][c], wss[c][s], as_);
        }
        int gn = nb + node;
        if (gn < N) {
            g_t[gn * 4 + s]  = at;
            g_sl[gn * 4 + s] = as_;
        }
    }
}

// ---------------------------------------------------------------------------
// Gather + softmax(4) + weighted combine. One warp per (n,k).
// Lane l does ONE uint4 load = 4 half2 = all 4 s-values for outputs (2l, 2l+1).
// ---------------------------------------------------------------------------
__global__ void __launch_bounds__(256) k_gather(const int* __restrict__ idx,
                                                float* __restrict__ out,
                                                int total /* N*K */)
{
    int w = (blockIdx.x * blockDim.x + threadIdx.x) >> 5;
    int lane = threadIdx.x & 31;
    if (w >= total) return;

    int n = w >> 4;                 // K = 16
    int j = __ldg(idx + w);

    float4 tv = __ldg((const float4*)g_t + n);
    float4 sv = __ldg((const float4*)g_sl + j);

    float l0 = tv.x + sv.x, l1 = tv.y + sv.y, l2 = tv.z + sv.z, l3 = tv.w + sv.w;
    float m = fmaxf(fmaxf(l0, l1), fmaxf(l2, l3));
    float e0 = __expf(l0 - m), e1 = __expf(l1 - m), e2 = __expf(l2 - m), e3 = __expf(l3 - m);
    float inv = 1.0f / (e0 + e1 + e2 + e3);
    float a0 = e0 * inv, a1 = e1 * inv, a2 = e2 * inv, a3 = e3 * inv;

    // one 16B load: {v_s0, v_s1, v_s2, v_s3} for outputs (2*lane, 2*lane+1)
    uint4 u = __ldg((const uint4*)(g_vh + j * 128) + lane);
    float2 f0 = __half22float2(*reinterpret_cast<__half2*>(&u.x));
    float2 f1 = __half22float2(*reinterpret_cast<__half2*>(&u.y));
    float2 f2 = __half22float2(*reinterpret_cast<__half2*>(&u.z));
    float2 f3 = __half22float2(*reinterpret_cast<__half2*>(&u.w));

    float2 r;
    r.x = a0 * f0.x + a1 * f1.x + a2 * f2.x + a3 * f3.x;
    r.y = a0 * f0.y + a1 * f1.y + a2 * f2.y + a3 * f3.y;

    ((float2*)out)[w * 32 + lane] = r;
}

// ---------------------------------------------------------------------------
extern "C" void kernel_launch(void* const* d_in, const int* in_sizes, int n_in,
                              void* d_out, int out_size)
{
    const float* x     = (const float*)d_in[0];
    const float* src   = (const float*)d_in[1];
    const int*   nidx  = (const int*)d_in[2];
    const float* Wt    = (const float*)d_in[3];
    const float* bt    = (const float*)d_in[4];
    const float* Ws    = (const float*)d_in[5];
    const float* bs    = (const float*)d_in[6];
    const float* W_lin = (const float*)d_in[7];
    const float* b_lin = (const float*)d_in[8];
    float* out = (float*)d_out;

    int N  = in_sizes[0] / CDIM;       // 50000
    int NK = in_sizes[2];              // N*K = 800000
    if (N > MAXN) N = MAXN;

    // 1) fused v-table + logits
    k_tables<<<VT_BLOCKS + LG_BLOCKS, 256>>>(x, src, Wt, bt, Ws, bs, W_lin, b_lin, N);

    // 2) gather + softmax + combine: one warp per (n,k)
    k_gather<<<(NK + 7) / 8, 256>>>(nidx, out, NK);
}

// round 4
// speedup vs baseline: 2.3591x; 2.3591x over previous
#include <cuda_runtime.h>
#include <cuda_fp16.h>

// Problem constants (fixed by dataset)
#define MAXN 50000
#define CDIM 64
#define SDIM 4
#define ODIM 64
#define KNEI 16

// Scratch (static __device__ — allocation-free per harness rules)
// v-table fp16: g_vh[j*128 + q*4 + s] = half2 of outputs (2q, 2q+1) of matrix s.
// One uint4 per (j, q) covers all 4 s for one output pair.
__device__ __half2 g_vh[MAXN * 128];          // 25.6 MB — L2 resident
__device__ float   g_t[MAXN * SDIM];          // x[n]@Wt + bt
__device__ float   g_sl[MAXN * SDIM];         // src[j]@Ws + bs
__device__ float4  g_a[MAXN * KNEI];          // softmax weights per (n,k), 12.8 MB

// ---------------------------------------------------------------------------
// Kernel 1: logits tables (unchanged from R2; 64 nodes / block via smem tiles)
// ---------------------------------------------------------------------------
__global__ void __launch_bounds__(256) k_logits(const float* __restrict__ x,
                                                const float* __restrict__ src,
                                                const float* __restrict__ Wt,
                                                const float* __restrict__ bt,
                                                const float* __restrict__ Ws,
                                                const float* __restrict__ bs,
                                                int N)
{
    __shared__ float xs[64][65];
    __shared__ float ss[64][65];
    __shared__ float wts[64][4];
    __shared__ float wss[64][4];

    int tid = threadIdx.x;
    int nb  = blockIdx.x * 64;

    wts[tid >> 2][tid & 3] = __ldg(Wt + tid);
    wss[tid >> 2][tid & 3] = __ldg(Ws + tid);

    for (int i = tid; i < 64 * 16; i += 256) {
        int row = i >> 4, c4 = i & 15;
        int node = nb + row;
        float4 xv = make_float4(0.f, 0.f, 0.f, 0.f);
        float4 sv = make_float4(0.f, 0.f, 0.f, 0.f);
        if (node < N) {
            xv = __ldg((const float4*)x + node * 16 + c4);
            sv = __ldg((const float4*)src + node * 16 + c4);
        }
        xs[row][c4 * 4 + 0] = xv.x; xs[row][c4 * 4 + 1] = xv.y;
        xs[row][c4 * 4 + 2] = xv.z; xs[row][c4 * 4 + 3] = xv.w;
        ss[row][c4 * 4 + 0] = sv.x; ss[row][c4 * 4 + 1] = sv.y;
        ss[row][c4 * 4 + 2] = sv.z; ss[row][c4 * 4 + 3] = sv.w;
    }
    __syncthreads();

    int node = tid >> 2;
    int s    = tid & 3;
    float at  = __ldg(bt + s);
    float as_ = __ldg(bs + s);
#pragma unroll
    for (int c = 0; c < CDIM; c++) {
        at  = fmaf(xs[node][c], wts[c][s], at);
        as_ = fmaf(ss[node][c], wss[c][s], as_);
    }
    int gn = nb + node;
    if (gn < N) {
        g_t[gn * 4 + s]  = at;
        g_sl[gn * 4 + s] = as_;
    }
}

// ---------------------------------------------------------------------------
// Kernel 2: v-table register-tiled SGEMM.
// Block tile: 64 j-rows x 256 outputs. Thread: 8 j x 8 outputs, where the 8
// outputs are the pair (2q, 2q+1) for all 4 matrices s (q = lane 0..31,
// warp jw = 0..7 owns j-octet jw*8..jw*8+7).
// src tile staged in smem (transposed, padded); weights via __ldg (L1-hot).
// Epilogue: one coalesced STG.128 per j per thread into the interleaved layout.
// ---------------------------------------------------------------------------
__global__ void __launch_bounds__(256, 2) k_vtable(const float* __restrict__ src,
                                                   const float* __restrict__ W_lin,  // [4,64,64]
                                                   const float* __restrict__ b_lin,  // [4,64]
                                                   int N)
{
    __shared__ float ss[64][68];   // ss[k][j], padded to kill staging conflicts

    int t  = threadIdx.x;
    int q  = t & 31;               // output pair id 0..31
    int jw = t >> 5;               // warp id 0..7 -> j-octet

    const float* wb = W_lin + 2 * q;
    float2 b0 = __ldg((const float2*)(b_lin + 0 * ODIM) + q);
    float2 b1 = __ldg((const float2*)(b_lin + 1 * ODIM) + q);
    float2 b2 = __ldg((const float2*)(b_lin + 2 * ODIM) + q);
    float2 b3 = __ldg((const float2*)(b_lin + 3 * ODIM) + q);
    b0.x *= 0.25f; b0.y *= 0.25f; b1.x *= 0.25f; b1.y *= 0.25f;
    b2.x *= 0.25f; b2.y *= 0.25f; b3.x *= 0.25f; b3.y *= 0.25f;

    int jrow = t >> 2;             // staging: thread loads row j0+jrow, quarter quad
    int quad = t & 3;

    for (int j0 = blockIdx.x * 64; j0 < N; j0 += gridDim.x * 64) {
        // ---- stage src tile (transposed) ----
        {
            int jg = j0 + jrow;
            const float4* srp = (const float4*)(src + (size_t)jg * CDIM) + quad * 4;
#pragma unroll
            for (int ii = 0; ii < 4; ii++) {
                float4 v = (jg < N) ? __ldg(srp + ii) : make_float4(0.f, 0.f, 0.f, 0.f);
                int kb = quad * 16 + ii * 4;
                ss[kb + 0][jrow] = v.x;
                ss[kb + 1][jrow] = v.y;
                ss[kb + 2][jrow] = v.z;
                ss[kb + 3][jrow] = v.w;
            }
        }
        __syncthreads();

        // ---- compute 8x8 microtile ----
        float ax[8][4], ay[8][4];
#pragma unroll
        for (int m = 0; m < 8; m++)
#pragma unroll
            for (int s = 0; s < 4; s++) { ax[m][s] = 0.f; ay[m][s] = 0.f; }

#pragma unroll 4
        for (int k = 0; k < CDIM; k++) {
            float2 w0 = __ldg((const float2*)(wb + k * 64));
            float2 w1 = __ldg((const float2*)(wb + 4096 + k * 64));
            float2 w2 = __ldg((const float2*)(wb + 8192 + k * 64));
            float2 w3 = __ldg((const float2*)(wb + 12288 + k * 64));
            float4 sA = *(const float4*)&ss[k][jw * 8];
            float4 sB = *(const float4*)&ss[k][jw * 8 + 4];
            float sj[8] = {sA.x, sA.y, sA.z, sA.w, sB.x, sB.y, sB.z, sB.w};
#pragma unroll
            for (int m = 0; m < 8; m++) {
                ax[m][0] = fmaf(sj[m], w0.x, ax[m][0]); ay[m][0] = fmaf(sj[m], w0.y, ay[m][0]);
                ax[m][1] = fmaf(sj[m], w1.x, ax[m][1]); ay[m][1] = fmaf(sj[m], w1.y, ay[m][1]);
                ax[m][2] = fmaf(sj[m], w2.x, ax[m][2]); ay[m][2] = fmaf(sj[m], w2.y, ay[m][2]);
                ax[m][3] = fmaf(sj[m], w3.x, ax[m][3]); ay[m][3] = fmaf(sj[m], w3.y, ay[m][3]);
            }
        }

        // ---- epilogue: fp16 pack, one STG.128 per j ----
#pragma unroll
        for (int m = 0; m < 8; m++) {
            int j = j0 + jw * 8 + m;
            if (j < N) {
                __half2 h0 = __floats2half2_rn(fmaf(ax[m][0], 0.25f, b0.x), fmaf(ay[m][0], 0.25f, b0.y));
                __half2 h1 = __floats2half2_rn(fmaf(ax[m][1], 0.25f, b1.x), fmaf(ay[m][1], 0.25f, b1.y));
                __half2 h2 = __floats2half2_rn(fmaf(ax[m][2], 0.25f, b2.x), fmaf(ay[m][2], 0.25f, b2.y));
                __half2 h3 = __floats2half2_rn(fmaf(ax[m][3], 0.25f, b3.x), fmaf(ay[m][3], 0.25f, b3.y));
                uint4 st;
                st.x = *reinterpret_cast<unsigned int*>(&h0);
                st.y = *reinterpret_cast<unsigned int*>(&h1);
                st.z = *reinterpret_cast<unsigned int*>(&h2);
                st.w = *reinterpret_cast<unsigned int*>(&h3);
                *reinterpret_cast<uint4*>(g_vh + (size_t)j * 128 + q * 4) = st;
            }
        }
        __syncthreads();
    }
}

// ---------------------------------------------------------------------------
// Kernel 3: softmax weights. One thread per (n,k).
// ---------------------------------------------------------------------------
__global__ void __launch_bounds__(256) k_soft(const int* __restrict__ idx, int total)
{
    int w = blockIdx.x * blockDim.x + threadIdx.x;
    if (w >= total) return;
    int n = w >> 4;                 // K = 16
    int j = __ldg(idx + w);

    float4 tv = __ldg((const float4*)g_t + n);
    float4 sv = __ldg((const float4*)g_sl + j);

    float l0 = tv.x + sv.x, l1 = tv.y + sv.y, l2 = tv.z + sv.z, l3 = tv.w + sv.w;
    float m = fmaxf(fmaxf(l0, l1), fmaxf(l2, l3));
    float e0 = __expf(l0 - m), e1 = __expf(l1 - m), e2 = __expf(l2 - m), e3 = __expf(l3 - m);
    float inv = 1.0f / (e0 + e1 + e2 + e3);
    g_a[w] = make_float4(e0 * inv, e1 * inv, e2 * inv, e3 * inv);
}

// ---------------------------------------------------------------------------
// Kernel 4: lean gather + combine. One warp per (n,k); lane q = output pair.
// ---------------------------------------------------------------------------
__global__ void __launch_bounds__(256) k_gather(const int* __restrict__ idx,
                                                float* __restrict__ out,
                                                int total /* N*K */)
{
    int w = (blockIdx.x * blockDim.x + threadIdx.x) >> 5;
    int lane = threadIdx.x & 31;
    if (w >= total) return;

    int j = __ldg(idx + w);
    float4 a = __ldg(g_a + w);      // warp-uniform broadcast

    uint4 u = __ldg((const uint4*)(g_vh + (size_t)j * 128) + lane);
    float2 f0 = __half22float2(*reinterpret_cast<__half2*>(&u.x));
    float2 f1 = __half22float2(*reinterpret_cast<__half2*>(&u.y));
    float2 f2 = __half22float2(*reinterpret_cast<__half2*>(&u.z));
    float2 f3 = __half22float2(*reinterpret_cast<__half2*>(&u.w));

    float2 r;
    r.x = a.x * f0.x + a.y * f1.x + a.z * f2.x + a.w * f3.x;
    r.y = a.x * f0.y + a.y * f1.y + a.z * f2.y + a.w * f3.y;

    ((float2*)out)[(size_t)w * 32 + lane] = r;
}

// ---------------------------------------------------------------------------
extern "C" void kernel_launch(void* const* d_in, const int* in_sizes, int n_in,
                              void* d_out, int out_size)
{
    const float* x     = (const float*)d_in[0];
    const float* src   = (const float*)d_in[1];
    const int*   nidx  = (const int*)d_in[2];
    const float* Wt    = (const float*)d_in[3];
    const float* bt    = (const float*)d_in[4];
    const float* Ws    = (const float*)d_in[5];
    const float* bs    = (const float*)d_in[6];
    const float* W_lin = (const float*)d_in[7];
    const float* b_lin = (const float*)d_in[8];
    float* out = (float*)d_out;

    int N  = in_sizes[0] / CDIM;       // 50000
    int NK = in_sizes[2];              // N*K = 800000
    if (N > MAXN) N = MAXN;

    k_logits<<<(N + 63) / 64, 256>>>(x, src, Wt, bt, Ws, bs, N);
    k_vtable<<<296, 256>>>(src, W_lin, b_lin, N);
    k_soft<<<(NK + 255) / 256, 256>>>(nidx, NK);
    k_gather<<<(NK + 7) / 8, 256>>>(nidx, out, NK);
}

// round 5
// speedup vs baseline: 3.5462x; 1.5032x over previous
#include <cuda_runtime.h>
#include <cuda_fp16.h>

// Problem constants (fixed by dataset)
#define MAXN 50000
#define CDIM 64
#define SDIM 4
#define ODIM 64
#define KNEI 16

// Scratch (static __device__ — allocation-free per harness rules)
// v-table fp16: g_vh[j*128 + q*4 + s] = half2 of outputs (2q, 2q+1) of matrix s.
__device__ __half2 g_vh[MAXN * 128];          // 25.6 MB — L2 resident
__device__ float   g_t[MAXN * SDIM];          // x[n]@Wt + bt
__device__ float   g_sl[MAXN * SDIM];         // src[j]@Ws + bs
__device__ float4  g_a[MAXN * KNEI];          // softmax weights per (n,k), 12.8 MB

// ---------------------------------------------------------------------------
// Fused kernel 1: role-split grid.
//   blocks [0, vtBlocks)            : v-table register-tiled SGEMM (FMA-bound)
//   blocks [vtBlocks, vtBlocks+lg)  : logits tables (hides under vtable)
// Shared memory is a union of the two roles' layouts.
// ---------------------------------------------------------------------------
__global__ void __launch_bounds__(256, 2) k_tables(const float* __restrict__ x,
                                                   const float* __restrict__ src,
                                                   const float* __restrict__ Wt,     // [64,4]
                                                   const float* __restrict__ bt,     // [4]
                                                   const float* __restrict__ Ws,     // [64,4]
                                                   const float* __restrict__ bs,     // [4]
                                                   const float* __restrict__ W_lin,  // [4,64,64]
                                                   const float* __restrict__ b_lin,  // [4,64]
                                                   int N, int vtBlocks)
{
    __shared__ __align__(16) char smraw[35328];   // max(vtable 17408, logits 35328)
    int t = threadIdx.x;

    if ((int)blockIdx.x < vtBlocks) {
        // ---------------- v-table role ----------------
        float (*ss)[68] = reinterpret_cast<float (*)[68]>(smraw);  // ss[k][j]

        int q  = t & 31;               // output pair id 0..31
        int jw = t >> 5;               // warp id 0..7 -> j-octet

        const float* wb = W_lin + 2 * q;
        float2 b0 = __ldg((const float2*)(b_lin + 0 * ODIM) + q);
        float2 b1 = __ldg((const float2*)(b_lin + 1 * ODIM) + q);
        float2 b2 = __ldg((const float2*)(b_lin + 2 * ODIM) + q);
        float2 b3 = __ldg((const float2*)(b_lin + 3 * ODIM) + q);
        b0.x *= 0.25f; b0.y *= 0.25f; b1.x *= 0.25f; b1.y *= 0.25f;
        b2.x *= 0.25f; b2.y *= 0.25f; b3.x *= 0.25f; b3.y *= 0.25f;

        int jrow = t >> 2;
        int quad = t & 3;
        int j0 = blockIdx.x * 64;

        // ---- stage src tile (transposed) ----
        {
            int jg = j0 + jrow;
            const float4* srp = (const float4*)(src + (size_t)jg * CDIM) + quad * 4;
#pragma unroll
            for (int ii = 0; ii < 4; ii++) {
                float4 v = (jg < N) ? __ldg(srp + ii) : make_float4(0.f, 0.f, 0.f, 0.f);
                int kb = quad * 16 + ii * 4;
                ss[kb + 0][jrow] = v.x;
                ss[kb + 1][jrow] = v.y;
                ss[kb + 2][jrow] = v.z;
                ss[kb + 3][jrow] = v.w;
            }
        }
        __syncthreads();

        // ---- compute 8x8 microtile ----
        float ax[8][4], ay[8][4];
#pragma unroll
        for (int m = 0; m < 8; m++)
#pragma unroll
            for (int s = 0; s < 4; s++) { ax[m][s] = 0.f; ay[m][s] = 0.f; }

#pragma unroll 4
        for (int k = 0; k < CDIM; k++) {
            float2 w0 = __ldg((const float2*)(wb + k * 64));
            float2 w1 = __ldg((const float2*)(wb + 4096 + k * 64));
            float2 w2 = __ldg((const float2*)(wb + 8192 + k * 64));
            float2 w3 = __ldg((const float2*)(wb + 12288 + k * 64));
            float4 sA = *(const float4*)&ss[k][jw * 8];
            float4 sB = *(const float4*)&ss[k][jw * 8 + 4];
            float sj[8] = {sA.x, sA.y, sA.z, sA.w, sB.x, sB.y, sB.z, sB.w};
#pragma unroll
            for (int m = 0; m < 8; m++) {
                ax[m][0] = fmaf(sj[m], w0.x, ax[m][0]); ay[m][0] = fmaf(sj[m], w0.y, ay[m][0]);
                ax[m][1] = fmaf(sj[m], w1.x, ax[m][1]); ay[m][1] = fmaf(sj[m], w1.y, ay[m][1]);
                ax[m][2] = fmaf(sj[m], w2.x, ax[m][2]); ay[m][2] = fmaf(sj[m], w2.y, ay[m][2]);
                ax[m][3] = fmaf(sj[m], w3.x, ax[m][3]); ay[m][3] = fmaf(sj[m], w3.y, ay[m][3]);
            }
        }

        // ---- epilogue: fp16 pack, one STG.128 per j ----
#pragma unroll
        for (int m = 0; m < 8; m++) {
            int j = j0 + jw * 8 + m;
            if (j < N) {
                __half2 h0 = __floats2half2_rn(fmaf(ax[m][0], 0.25f, b0.x), fmaf(ay[m][0], 0.25f, b0.y));
                __half2 h1 = __floats2half2_rn(fmaf(ax[m][1], 0.25f, b1.x), fmaf(ay[m][1], 0.25f, b1.y));
                __half2 h2 = __floats2half2_rn(fmaf(ax[m][2], 0.25f, b2.x), fmaf(ay[m][2], 0.25f, b2.y));
                __half2 h3 = __floats2half2_rn(fmaf(ax[m][3], 0.25f, b3.x), fmaf(ay[m][3], 0.25f, b3.y));
                uint4 st;
                st.x = *reinterpret_cast<unsigned int*>(&h0);
                st.y = *reinterpret_cast<unsigned int*>(&h1);
                st.z = *reinterpret_cast<unsigned int*>(&h2);
                st.w = *reinterpret_cast<unsigned int*>(&h3);
                *reinterpret_cast<uint4*>(g_vh + (size_t)j * 128 + q * 4) = st;
            }
        }
    } else {
        // ---------------- logits role ----------------
        float (*xs)[65]  = reinterpret_cast<float (*)[65]>(smraw);
        float (*ssl)[65] = reinterpret_cast<float (*)[65]>(smraw + 16640);
        float (*wts)[4]  = reinterpret_cast<float (*)[4]>(smraw + 33280);
        float (*wss)[4]  = reinterpret_cast<float (*)[4]>(smraw + 34304);

        int nb = (blockIdx.x - vtBlocks) * 64;

        wts[t >> 2][t & 3] = __ldg(Wt + t);
        wss[t >> 2][t & 3] = __ldg(Ws + t);

        for (int i = t; i < 64 * 16; i += 256) {
            int row = i >> 4, c4 = i & 15;
            int node = nb + row;
            float4 xv = make_float4(0.f, 0.f, 0.f, 0.f);
            float4 sv = make_float4(0.f, 0.f, 0.f, 0.f);
            if (node < N) {
                xv = __ldg((const float4*)x + node * 16 + c4);
                sv = __ldg((const float4*)src + node * 16 + c4);
            }
            xs[row][c4 * 4 + 0] = xv.x;  xs[row][c4 * 4 + 1] = xv.y;
            xs[row][c4 * 4 + 2] = xv.z;  xs[row][c4 * 4 + 3] = xv.w;
            ssl[row][c4 * 4 + 0] = sv.x; ssl[row][c4 * 4 + 1] = sv.y;
            ssl[row][c4 * 4 + 2] = sv.z; ssl[row][c4 * 4 + 3] = sv.w;
        }
        __syncthreads();

        int node = t >> 2;
        int s    = t & 3;
        float at  = __ldg(bt + s);
        float as_ = __ldg(bs + s);
#pragma unroll
        for (int c = 0; c < CDIM; c++) {
            at  = fmaf(xs[node][c], wts[c][s], at);
            as_ = fmaf(ssl[node][c], wss[c][s], as_);
        }
        int gn = nb + node;
        if (gn < N) {
            g_t[gn * 4 + s]  = at;
            g_sl[gn * 4 + s] = as_;
        }
    }
}

// ---------------------------------------------------------------------------
// Kernel 2: softmax weights. One thread per (n,k).
// ---------------------------------------------------------------------------
__global__ void __launch_bounds__(256) k_soft(const int* __restrict__ idx, int total)
{
    int w = blockIdx.x * blockDim.x + threadIdx.x;
    if (w >= total) return;
    int n = w >> 4;                 // K = 16
    int j = __ldg(idx + w);

    float4 tv = __ldg((const float4*)g_t + n);
    float4 sv = __ldg((const float4*)g_sl + j);

    float l0 = tv.x + sv.x, l1 = tv.y + sv.y, l2 = tv.z + sv.z, l3 = tv.w + sv.w;
    float m = fmaxf(fmaxf(l0, l1), fmaxf(l2, l3));
    float e0 = __expf(l0 - m), e1 = __expf(l1 - m), e2 = __expf(l2 - m), e3 = __expf(l3 - m);
    float inv = 1.0f / (e0 + e1 + e2 + e3);
    g_a[w] = make_float4(e0 * inv, e1 * inv, e2 * inv, e3 * inv);
}

// ---------------------------------------------------------------------------
// Kernel 3: gather + combine, 4 pairs per warp (batched for MLP + amortized
// addressing). Lane q owns output pair (2q, 2q+1). Streaming stores.
// ---------------------------------------------------------------------------
__global__ void __launch_bounds__(256) k_gather(const int* __restrict__ idx,
                                                float* __restrict__ out,
                                                int total /* N*K */)
{
    int lane = threadIdx.x & 31;
    int gw   = (blockIdx.x * blockDim.x + threadIdx.x) >> 5;
    int w    = gw * 4;
    if (w >= total) return;

    if (w + 3 < total) {
        int4 jj = __ldg((const int4*)idx + gw);            // 4 neighbor ids, uniform
        float4 a0 = __ldg(g_a + w + 0);
        float4 a1 = __ldg(g_a + w + 1);
        float4 a2 = __ldg(g_a + w + 2);
        float4 a3 = __ldg(g_a + w + 3);

        uint4 u0 = __ldg((const uint4*)(g_vh + (size_t)jj.x * 128) + lane);
        uint4 u1 = __ldg((const uint4*)(g_vh + (size_t)jj.y * 128) + lane);
        uint4 u2 = __ldg((const uint4*)(g_vh + (size_t)jj.z * 128) + lane);
        uint4 u3 = __ldg((const uint4*)(g_vh + (size_t)jj.w * 128) + lane);

        float2* ob = (float2*)out + (size_t)w * 32 + lane;

#define COMBINE(U, A, OFF)                                                       \
        {                                                                        \
            float2 f0 = __half22float2(*reinterpret_cast<__half2*>(&U.x));       \
            float2 f1 = __half22float2(*reinterpret_cast<__half2*>(&U.y));       \
            float2 f2 = __half22float2(*reinterpret_cast<__half2*>(&U.z));       \
            float2 f3 = __half22float2(*reinterpret_cast<__half2*>(&U.w));       \
            float2 r;                                                            \
            r.x = A.x * f0.x + A.y * f1.x + A.z * f2.x + A.w * f3.x;             \
            r.y = A.x * f0.y + A.y * f1.y + A.z * f2.y + A.w * f3.y;             \
            __stcs(ob + (OFF) * 32, r);                                          \
        }
        COMBINE(u0, a0, 0)
        COMBINE(u1, a1, 1)
        COMBINE(u2, a2, 2)
        COMBINE(u3, a3, 3)
#undef COMBINE
    } else {
        for (int i = 0; i < 4 && w + i < total; i++) {
            int wi = w + i;
            int j = __ldg(idx + wi);
            float4 a = __ldg(g_a + wi);
            uint4 u = __ldg((const uint4*)(g_vh + (size_t)j * 128) + lane);
            float2 f0 = __half22float2(*reinterpret_cast<__half2*>(&u.x));
            float2 f1 = __half22float2(*reinterpret_cast<__half2*>(&u.y));
            float2 f2 = __half22float2(*reinterpret_cast<__half2*>(&u.z));
            float2 f3 = __half22float2(*reinterpret_cast<__half2*>(&u.w));
            float2 r;
            r.x = a.x * f0.x + a.y * f1.x + a.z * f2.x + a.w * f3.x;
            r.y = a.x * f0.y + a.y * f1.y + a.z * f2.y + a.w * f3.y;
            __stcs((float2*)out + (size_t)wi * 32 + lane, r);
        }
    }
}

// ---------------------------------------------------------------------------
extern "C" void kernel_launch(void* const* d_in, const int* in_sizes, int n_in,
                              void* d_out, int out_size)
{
    const float* x     = (const float*)d_in[0];
    const float* src   = (const float*)d_in[1];
    const int*   nidx  = (const int*)d_in[2];
    const float* Wt    = (const float*)d_in[3];
    const float* bt    = (const float*)d_in[4];
    const float* Ws    = (const float*)d_in[5];
    const float* bs    = (const float*)d_in[6];
    const float* W_lin = (const float*)d_in[7];
    const float* b_lin = (const float*)d_in[8];
    float* out = (float*)d_out;

    int N  = in_sizes[0] / CDIM;       // 50000
    int NK = in_sizes[2];              // N*K = 800000
    if (N > MAXN) N = MAXN;

    int tiles = (N + 63) / 64;         // 782

    // 1) fused v-table + logits (logits hides under FMA-bound vtable)
    k_tables<<<2 * tiles, 256>>>(x, src, Wt, bt, Ws, bs, W_lin, b_lin, N, tiles);

    // 2) softmax weights
    k_soft<<<(NK + 255) / 256, 256>>>(nidx, NK);

    // 3) gather + combine: 4 pairs per warp
    int gwarps = (NK + 3) / 4;
    k_gather<<<(gwarps + 7) / 8, 256>>>(nidx, out, NK);
}

// round 6
// speedup vs baseline: 3.6821x; 1.0383x over previous
#include <cuda_runtime.h>
#include <cuda_fp16.h>

// Problem constants (fixed by dataset)
#define MAXN 50000
#define CDIM 64
#define SDIM 4
#define ODIM 64
#define KNEI 16

// Scratch (static __device__ — allocation-free per harness rules)
// v-table fp16: g_vh[j*128 + q*4 + s] = half2 of outputs (2q, 2q+1) of matrix s.
__device__ __half2 g_vh[MAXN * 128];          // 25.6 MB — L2 resident
__device__ float   g_t[MAXN * SDIM];          // x[n]@Wt + bt
__device__ float   g_sl[MAXN * SDIM];         // src[j]@Ws + bs
__device__ float4  g_a[MAXN * KNEI];          // softmax weights per (n,k), 12.8 MB

__device__ __forceinline__ unsigned long long fma2(unsigned long long a,
                                                   unsigned long long b,
                                                   unsigned long long c) {
    unsigned long long d;
    asm("fma.rn.f32x2 %0, %1, %2, %3;" : "=l"(d) : "l"(a), "l"(b), "l"(c));
    return d;
}

// ---------------------------------------------------------------------------
// Fused kernel 1: role-split grid.
//   blocks [0, vtBlocks)            : v-table register-tiled SGEMM (FFMA2)
//   blocks [vtBlocks, vtBlocks+lg)  : logits tables (hides under vtable)
// ---------------------------------------------------------------------------
__global__ void __launch_bounds__(256, 2) k_tables(const float* __restrict__ x,
                                                   const float* __restrict__ src,
                                                   const float* __restrict__ Wt,     // [64,4]
                                                   const float* __restrict__ bt,     // [4]
                                                   const float* __restrict__ Ws,     // [64,4]
                                                   const float* __restrict__ bs,     // [4]
                                                   const float* __restrict__ W_lin,  // [4,64,64]
                                                   const float* __restrict__ b_lin,  // [4,64]
                                                   int N, int vtBlocks)
{
    __shared__ __align__(16) char smraw[35328];   // max(vtable 17408, logits 35328)
    int t = threadIdx.x;

    if ((int)blockIdx.x < vtBlocks) {
        // ---------------- v-table role ----------------
        float (*ss)[68] = reinterpret_cast<float (*)[68]>(smraw);  // ss[k][j]

        int q  = t & 31;               // output pair id 0..31
        int jw = t >> 5;               // warp id 0..7 -> j-octet

        const float* wb = W_lin + 2 * q;   // 8B-aligned (q pairs)
        float2 b0 = __ldg((const float2*)(b_lin + 0 * ODIM) + q);
        float2 b1 = __ldg((const float2*)(b_lin + 1 * ODIM) + q);
        float2 b2 = __ldg((const float2*)(b_lin + 2 * ODIM) + q);
        float2 b3 = __ldg((const float2*)(b_lin + 3 * ODIM) + q);
        b0.x *= 0.25f; b0.y *= 0.25f; b1.x *= 0.25f; b1.y *= 0.25f;
        b2.x *= 0.25f; b2.y *= 0.25f; b3.x *= 0.25f; b3.y *= 0.25f;

        int jrow = t >> 2;
        int quad = t & 3;
        int j0 = blockIdx.x * 64;

        // ---- stage src tile (transposed) ----
        {
            int jg = j0 + jrow;
            const float4* srp = (const float4*)(src + (size_t)jg * CDIM) + quad * 4;
#pragma unroll
            for (int ii = 0; ii < 4; ii++) {
                float4 v = (jg < N) ? __ldg(srp + ii) : make_float4(0.f, 0.f, 0.f, 0.f);
                int kb = quad * 16 + ii * 4;
                ss[kb + 0][jrow] = v.x;
                ss[kb + 1][jrow] = v.y;
                ss[kb + 2][jrow] = v.z;
                ss[kb + 3][jrow] = v.w;
            }
        }
        __syncthreads();

        // ---- compute 8j x 8out microtile with packed f32x2 FMA ----
        // acc[m][s] = pair (out 2q, out 2q+1) for matrix s, row j0+jw*8+m
        unsigned long long acc[8][4];
#pragma unroll
        for (int m = 0; m < 8; m++)
#pragma unroll
            for (int s = 0; s < 4; s++) acc[m][s] = 0ull;

#pragma unroll 4
        for (int k = 0; k < CDIM; k++) {
            // weight pairs loaded directly as 64-bit (LDG.64, no pack)
            unsigned long long W0 = __ldg((const unsigned long long*)(wb + k * 64));
            unsigned long long W1 = __ldg((const unsigned long long*)(wb + 4096 + k * 64));
            unsigned long long W2 = __ldg((const unsigned long long*)(wb + 8192 + k * 64));
            unsigned long long W3 = __ldg((const unsigned long long*)(wb + 12288 + k * 64));
            float4 sA = *(const float4*)&ss[k][jw * 8];
            float4 sB = *(const float4*)&ss[k][jw * 8 + 4];
            float sj[8] = {sA.x, sA.y, sA.z, sA.w, sB.x, sB.y, sB.z, sB.w};
#pragma unroll
            for (int m = 0; m < 8; m++) {
                unsigned long long p;   // broadcast pair {sj, sj} — one ALU pack
                asm("mov.b64 %0, {%1, %1};" : "=l"(p) : "r"(__float_as_uint(sj[m])));
                acc[m][0] = fma2(W0, p, acc[m][0]);
                acc[m][1] = fma2(W1, p, acc[m][1]);
                acc[m][2] = fma2(W2, p, acc[m][2]);
                acc[m][3] = fma2(W3, p, acc[m][3]);
            }
        }

        // ---- epilogue: unpack, scale+bias, fp16 pack, one STG.128 per j ----
#pragma unroll
        for (int m = 0; m < 8; m++) {
            int j = j0 + jw * 8 + m;
            if (j < N) {
                float vx[4], vy[4];
#pragma unroll
                for (int s = 0; s < 4; s++) {
                    unsigned int lo, hi;
                    asm("mov.b64 {%0, %1}, %2;" : "=r"(lo), "=r"(hi) : "l"(acc[m][s]));
                    vx[s] = __uint_as_float(lo);
                    vy[s] = __uint_as_float(hi);
                }
                __half2 h0 = __floats2half2_rn(fmaf(vx[0], 0.25f, b0.x), fmaf(vy[0], 0.25f, b0.y));
                __half2 h1 = __floats2half2_rn(fmaf(vx[1], 0.25f, b1.x), fmaf(vy[1], 0.25f, b1.y));
                __half2 h2 = __floats2half2_rn(fmaf(vx[2], 0.25f, b2.x), fmaf(vy[2], 0.25f, b2.y));
                __half2 h3 = __floats2half2_rn(fmaf(vx[3], 0.25f, b3.x), fmaf(vy[3], 0.25f, b3.y));
                uint4 st;
                st.x = *reinterpret_cast<unsigned int*>(&h0);
                st.y = *reinterpret_cast<unsigned int*>(&h1);
                st.z = *reinterpret_cast<unsigned int*>(&h2);
                st.w = *reinterpret_cast<unsigned int*>(&h3);
                *reinterpret_cast<uint4*>(g_vh + (size_t)j * 128 + q * 4) = st;
            }
        }
    } else {
        // ---------------- logits role ----------------
        float (*xs)[65]  = reinterpret_cast<float (*)[65]>(smraw);
        float (*ssl)[65] = reinterpret_cast<float (*)[65]>(smraw + 16640);
        float (*wts)[4]  = reinterpret_cast<float (*)[4]>(smraw + 33280);
        float (*wss)[4]  = reinterpret_cast<float (*)[4]>(smraw + 34304);

        int nb = (blockIdx.x - vtBlocks) * 64;

        wts[t >> 2][t & 3] = __ldg(Wt + t);
        wss[t >> 2][t & 3] = __ldg(Ws + t);

        for (int i = t; i < 64 * 16; i += 256) {
            int row = i >> 4, c4 = i & 15;
            int node = nb + row;
            float4 xv = make_float4(0.f, 0.f, 0.f, 0.f);
            float4 sv = make_float4(0.f, 0.f, 0.f, 0.f);
            if (node < N) {
                xv = __ldg((const float4*)x + node * 16 + c4);
                sv = __ldg((const float4*)src + node * 16 + c4);
            }
            xs[row][c4 * 4 + 0] = xv.x;  xs[row][c4 * 4 + 1] = xv.y;
            xs[row][c4 * 4 + 2] = xv.z;  xs[row][c4 * 4 + 3] = xv.w;
            ssl[row][c4 * 4 + 0] = sv.x; ssl[row][c4 * 4 + 1] = sv.y;
            ssl[row][c4 * 4 + 2] = sv.z; ssl[row][c4 * 4 + 3] = sv.w;
        }
        __syncthreads();

        int node = t >> 2;
        int s    = t & 3;
        float at  = __ldg(bt + s);
        float as_ = __ldg(bs + s);
#pragma unroll
        for (int c = 0; c < CDIM; c++) {
            at  = fmaf(xs[node][c], wts[c][s], at);
            as_ = fmaf(ssl[node][c], wss[c][s], as_);
        }
        int gn = nb + node;
        if (gn < N) {
            g_t[gn * 4 + s]  = at;
            g_sl[gn * 4 + s] = as_;
        }
    }
}

// ---------------------------------------------------------------------------
// Kernel 2: softmax weights. One thread per (n,k).
// ---------------------------------------------------------------------------
__global__ void __launch_bounds__(256) k_soft(const int* __restrict__ idx, int total)
{
    int w = blockIdx.x * blockDim.x + threadIdx.x;
    if (w >= total) return;
    int n = w >> 4;                 // K = 16
    int j = __ldg(idx + w);

    float4 tv = __ldg((const float4*)g_t + n);
    float4 sv = __ldg((const float4*)g_sl + j);

    float l0 = tv.x + sv.x, l1 = tv.y + sv.y, l2 = tv.z + sv.z, l3 = tv.w + sv.w;
    float m = fmaxf(fmaxf(l0, l1), fmaxf(l2, l3));
    float e0 = __expf(l0 - m), e1 = __expf(l1 - m), e2 = __expf(l2 - m), e3 = __expf(l3 - m);
    float inv = 1.0f / (e0 + e1 + e2 + e3);
    g_a[w] = make_float4(e0 * inv, e1 * inv, e2 * inv, e3 * inv);
}

// ---------------------------------------------------------------------------
// Kernel 3: gather + combine, 4 pairs per warp. Streaming stores.
// ---------------------------------------------------------------------------
__global__ void __launch_bounds__(256) k_gather(const int* __restrict__ idx,
                                                float* __restrict__ out,
                                                int total /* N*K */)
{
    int lane = threadIdx.x & 31;
    int gw   = (blockIdx.x * blockDim.x + threadIdx.x) >> 5;
    int w    = gw * 4;
    if (w >= total) return;

    if (w + 3 < total) {
        int4 jj = __ldg((const int4*)idx + gw);            // 4 neighbor ids, uniform
        float4 a0 = __ldg(g_a + w + 0);
        float4 a1 = __ldg(g_a + w + 1);
        float4 a2 = __ldg(g_a + w + 2);
        float4 a3 = __ldg(g_a + w + 3);

        uint4 u0 = __ldg((const uint4*)(g_vh + (size_t)jj.x * 128) + lane);
        uint4 u1 = __ldg((const uint4*)(g_vh + (size_t)jj.y * 128) + lane);
        uint4 u2 = __ldg((const uint4*)(g_vh + (size_t)jj.z * 128) + lane);
        uint4 u3 = __ldg((const uint4*)(g_vh + (size_t)jj.w * 128) + lane);

        float2* ob = (float2*)out + (size_t)w * 32 + lane;

#define COMBINE(U, A, OFF)                                                       \
        {                                                                        \
            float2 f0 = __half22float2(*reinterpret_cast<__half2*>(&U.x));       \
            float2 f1 = __half22float2(*reinterpret_cast<__half2*>(&U.y));       \
            float2 f2 = __half22float2(*reinterpret_cast<__half2*>(&U.z));       \
            float2 f3 = __half22float2(*reinterpret_cast<__half2*>(&U.w));       \
            float2 r;                                                            \
            r.x = A.x * f0.x + A.y * f1.x + A.z * f2.x + A.w * f3.x;             \
            r.y = A.x * f0.y + A.y * f1.y + A.z * f2.y + A.w * f3.y;             \
            __stcs(ob + (OFF) * 32, r);                                          \
        }
        COMBINE(u0, a0, 0)
        COMBINE(u1, a1, 1)
        COMBINE(u2, a2, 2)
        COMBINE(u3, a3, 3)
#undef COMBINE
    } else {
        for (int i = 0; i < 4 && w + i < total; i++) {
            int wi = w + i;
            int j = __ldg(idx + wi);
            float4 a = __ldg(g_a + wi);
            uint4 u = __ldg((const uint4*)(g_vh + (size_t)j * 128) + lane);
            float2 f0 = __half22float2(*reinterpret_cast<__half2*>(&u.x));
            float2 f1 = __half22float2(*reinterpret_cast<__half2*>(&u.y));
            float2 f2 = __half22float2(*reinterpret_cast<__half2*>(&u.z));
            float2 f3 = __half22float2(*reinterpret_cast<__half2*>(&u.w));
            float2 r;
            r.x = a.x * f0.x + a.y * f1.x + a.z * f2.x + a.w * f3.x;
            r.y = a.x * f0.y + a.y * f1.y + a.z * f2.y + a.w * f3.y;
            __stcs((float2*)out + (size_t)wi * 32 + lane, r);
        }
    }
}

// ---------------------------------------------------------------------------
extern "C" void kernel_launch(void* const* d_in, const int* in_sizes, int n_in,
                              void* d_out, int out_size)
{
    const float* x     = (const float*)d_in[0];
    const float* src   = (const float*)d_in[1];
    const int*   nidx  = (const int*)d_in[2];
    const float* Wt    = (const float*)d_in[3];
    const float* bt    = (const float*)d_in[4];
    const float* Ws    = (const float*)d_in[5];
    const float* bs    = (const float*)d_in[6];
    const float* W_lin = (const float*)d_in[7];
    const float* b_lin = (const float*)d_in[8];
    float* out = (float*)d_out;

    int N  = in_sizes[0] / CDIM;       // 50000
    int NK = in_sizes[2];              // N*K = 800000
    if (N > MAXN) N = MAXN;

    int tiles = (N + 63) / 64;         // 782

    // 1) fused v-table + logits (logits hides under FMA-bound vtable)
    k_tables<<<2 * tiles, 256>>>(x, src, Wt, bt, Ws, bs, W_lin, b_lin, N, tiles);

    // 2) softmax weights
    k_soft<<<(NK + 255) / 256, 256>>>(nidx, NK);

    // 3) gather + combine: 4 pairs per warp
    int gwarps = (NK + 3) / 4;
    k_gather<<<(gwarps + 7) / 8, 256>>>(nidx, out, NK);
}

// round 7
// speedup vs baseline: 4.0800x; 1.1081x over previous
#include <cuda_runtime.h>
#include <cuda_fp16.h>

// Problem constants (fixed by dataset)
#define MAXN 50000
#define CDIM 64
#define SDIM 4
#define ODIM 64
#define KNEI 16

// Scratch (static __device__ — allocation-free per harness rules)
// v-table fp16: g_vh[j*128 + q*4 + s] = half2 of outputs (2q, 2q+1) of matrix s.
__device__ __half2 g_vh[MAXN * 128];          // 25.6 MB — L2 resident
__device__ float   g_t[MAXN * SDIM];          // x[n]@Wt + bt
__device__ float   g_sl[MAXN * SDIM];         // src[j]@Ws + bs

__device__ __forceinline__ unsigned long long fma2(unsigned long long a,
                                                   unsigned long long b,
                                                   unsigned long long c) {
    unsigned long long d;
    asm("fma.rn.f32x2 %0, %1, %2, %3;" : "=l"(d) : "l"(a), "l"(b), "l"(c));
    return d;
}

// ---------------------------------------------------------------------------
// Fused kernel 1: role-split grid.
//   blocks [0, vtBlocks)            : v-table register-tiled SGEMM (FFMA2)
//   blocks [vtBlocks, vtBlocks+lg)  : logits tables (hides under vtable)
// ---------------------------------------------------------------------------
__global__ void __launch_bounds__(256, 2) k_tables(const float* __restrict__ x,
                                                   const float* __restrict__ src,
                                                   const float* __restrict__ Wt,     // [64,4]
                                                   const float* __restrict__ bt,     // [4]
                                                   const float* __restrict__ Ws,     // [64,4]
                                                   const float* __restrict__ bs,     // [4]
                                                   const float* __restrict__ W_lin,  // [4,64,64]
                                                   const float* __restrict__ b_lin,  // [4,64]
                                                   int N, int vtBlocks)
{
    __shared__ __align__(16) char smraw[35328];   // max(vtable 17408, logits 35328)
    int t = threadIdx.x;

    if ((int)blockIdx.x < vtBlocks) {
        // ---------------- v-table role ----------------
        float (*ss)[68] = reinterpret_cast<float (*)[68]>(smraw);  // ss[k][j]

        int q  = t & 31;               // output pair id 0..31
        int jw = t >> 5;               // warp id 0..7 -> j-octet

        const float* wb = W_lin + 2 * q;   // 8B-aligned (q pairs)
        float2 b0 = __ldg((const float2*)(b_lin + 0 * ODIM) + q);
        float2 b1 = __ldg((const float2*)(b_lin + 1 * ODIM) + q);
        float2 b2 = __ldg((const float2*)(b_lin + 2 * ODIM) + q);
        float2 b3 = __ldg((const float2*)(b_lin + 3 * ODIM) + q);
        b0.x *= 0.25f; b0.y *= 0.25f; b1.x *= 0.25f; b1.y *= 0.25f;
        b2.x *= 0.25f; b2.y *= 0.25f; b3.x *= 0.25f; b3.y *= 0.25f;

        int jrow = t >> 2;
        int quad = t & 3;
        int j0 = blockIdx.x * 64;

        // ---- stage src tile (transposed) ----
        {
            int jg = j0 + jrow;
            const float4* srp = (const float4*)(src + (size_t)jg * CDIM) + quad * 4;
#pragma unroll
            for (int ii = 0; ii < 4; ii++) {
                float4 v = (jg < N) ? __ldg(srp + ii) : make_float4(0.f, 0.f, 0.f, 0.f);
                int kb = quad * 16 + ii * 4;
                ss[kb + 0][jrow] = v.x;
                ss[kb + 1][jrow] = v.y;
                ss[kb + 2][jrow] = v.z;
                ss[kb + 3][jrow] = v.w;
            }
        }
        __syncthreads();

        // ---- compute 8j x 8out microtile with packed f32x2 FMA ----
        unsigned long long acc[8][4];
#pragma unroll
        for (int m = 0; m < 8; m++)
#pragma unroll
            for (int s = 0; s < 4; s++) acc[m][s] = 0ull;

#pragma unroll 4
        for (int k = 0; k < CDIM; k++) {
            unsigned long long W0 = __ldg((const unsigned long long*)(wb + k * 64));
            unsigned long long W1 = __ldg((const unsigned long long*)(wb + 4096 + k * 64));
            unsigned long long W2 = __ldg((const unsigned long long*)(wb + 8192 + k * 64));
            unsigned long long W3 = __ldg((const unsigned long long*)(wb + 12288 + k * 64));
            float4 sA = *(const float4*)&ss[k][jw * 8];
            float4 sB = *(const float4*)&ss[k][jw * 8 + 4];
            float sj[8] = {sA.x, sA.y, sA.z, sA.w, sB.x, sB.y, sB.z, sB.w};
#pragma unroll
            for (int m = 0; m < 8; m++) {
                unsigned long long p;   // broadcast pair {sj, sj} — one ALU pack
                asm("mov.b64 %0, {%1, %1};" : "=l"(p) : "r"(__float_as_uint(sj[m])));
                acc[m][0] = fma2(W0, p, acc[m][0]);
                acc[m][1] = fma2(W1, p, acc[m][1]);
                acc[m][2] = fma2(W2, p, acc[m][2]);
                acc[m][3] = fma2(W3, p, acc[m][3]);
            }
        }

        // ---- epilogue: unpack, scale+bias, fp16 pack, one STG.128 per j ----
#pragma unroll
        for (int m = 0; m < 8; m++) {
            int j = j0 + jw * 8 + m;
            if (j < N) {
                float vx[4], vy[4];
#pragma unroll
                for (int s = 0; s < 4; s++) {
                    unsigned int lo, hi;
                    asm("mov.b64 {%0, %1}, %2;" : "=r"(lo), "=r"(hi) : "l"(acc[m][s]));
                    vx[s] = __uint_as_float(lo);
                    vy[s] = __uint_as_float(hi);
                }
                __half2 h0 = __floats2half2_rn(fmaf(vx[0], 0.25f, b0.x), fmaf(vy[0], 0.25f, b0.y));
                __half2 h1 = __floats2half2_rn(fmaf(vx[1], 0.25f, b1.x), fmaf(vy[1], 0.25f, b1.y));
                __half2 h2 = __floats2half2_rn(fmaf(vx[2], 0.25f, b2.x), fmaf(vy[2], 0.25f, b2.y));
                __half2 h3 = __floats2half2_rn(fmaf(vx[3], 0.25f, b3.x), fmaf(vy[3], 0.25f, b3.y));
                uint4 st;
                st.x = *reinterpret_cast<unsigned int*>(&h0);
                st.y = *reinterpret_cast<unsigned int*>(&h1);
                st.z = *reinterpret_cast<unsigned int*>(&h2);
                st.w = *reinterpret_cast<unsigned int*>(&h3);
                *reinterpret_cast<uint4*>(g_vh + (size_t)j * 128 + q * 4) = st;
            }
        }
    } else {
        // ---------------- logits role ----------------
        float (*xs)[65]  = reinterpret_cast<float (*)[65]>(smraw);
        float (*ssl)[65] = reinterpret_cast<float (*)[65]>(smraw + 16640);
        float (*wts)[4]  = reinterpret_cast<float (*)[4]>(smraw + 33280);
        float (*wss)[4]  = reinterpret_cast<float (*)[4]>(smraw + 34304);

        int nb = (blockIdx.x - vtBlocks) * 64;

        wts[t >> 2][t & 3] = __ldg(Wt + t);
        wss[t >> 2][t & 3] = __ldg(Ws + t);

        for (int i = t; i < 64 * 16; i += 256) {
            int row = i >> 4, c4 = i & 15;
            int node = nb + row;
            float4 xv = make_float4(0.f, 0.f, 0.f, 0.f);
            float4 sv = make_float4(0.f, 0.f, 0.f, 0.f);
            if (node < N) {
                xv = __ldg((const float4*)x + node * 16 + c4);
                sv = __ldg((const float4*)src + node * 16 + c4);
            }
            xs[row][c4 * 4 + 0] = xv.x;  xs[row][c4 * 4 + 1] = xv.y;
            xs[row][c4 * 4 + 2] = xv.z;  xs[row][c4 * 4 + 3] = xv.w;
            ssl[row][c4 * 4 + 0] = sv.x; ssl[row][c4 * 4 + 1] = sv.y;
            ssl[row][c4 * 4 + 2] = sv.z; ssl[row][c4 * 4 + 3] = sv.w;
        }
        __syncthreads();

        int node = t >> 2;
        int s    = t & 3;
        float at  = __ldg(bt + s);
        float as_ = __ldg(bs + s);
#pragma unroll
        for (int c = 0; c < CDIM; c++) {
            at  = fmaf(xs[node][c], wts[c][s], at);
            as_ = fmaf(ssl[node][c], wss[c][s], as_);
        }
        int gn = nb + node;
        if (gn < N) {
            g_t[gn * 4 + s]  = at;
            g_sl[gn * 4 + s] = as_;
        }
    }
}

// ---------------------------------------------------------------------------
// Kernel 2: fused softmax + gather + combine, 8 pairs per warp.
// Lanes 0..7 each compute one pair's softmax (g_t uniform: all 8 pairs share
// node n because w is 8-aligned and K=16); weights broadcast via shfl.
// Lane q owns output pair (2q, 2q+1). Streaming stores for out.
// ---------------------------------------------------------------------------
__global__ void __launch_bounds__(256) k_gather(const int* __restrict__ idx,
                                                float* __restrict__ out,
                                                int total /* N*K */)
{
    int lane = threadIdx.x & 31;
    int gw   = (blockIdx.x * blockDim.x + threadIdx.x) >> 5;
    int w    = gw * 8;
    if (w >= total) return;

    int n = w >> 4;                         // same node for all 8 pairs
    float4 tv = __ldg((const float4*)g_t + n);   // uniform

    // lanes 0..7: softmax for pair w+lane
    int   myj = 0;
    float4 a4 = make_float4(0.f, 0.f, 0.f, 0.f);
    if (lane < 8) {
        int wi = w + lane;
        if (wi < total) {
            myj = __ldg(idx + wi);
            float4 sv = __ldg((const float4*)g_sl + myj);
            float l0 = tv.x + sv.x, l1 = tv.y + sv.y;
            float l2 = tv.z + sv.z, l3 = tv.w + sv.w;
            float m = fmaxf(fmaxf(l0, l1), fmaxf(l2, l3));
            float e0 = __expf(l0 - m), e1 = __expf(l1 - m);
            float e2 = __expf(l2 - m), e3 = __expf(l3 - m);
            float inv = 1.0f / (e0 + e1 + e2 + e3);
            a4 = make_float4(e0 * inv, e1 * inv, e2 * inv, e3 * inv);
        }
    }

    if (w + 7 < total) {
        float2* ob = (float2*)out + (size_t)w * 32 + lane;
#pragma unroll
        for (int p = 0; p < 8; p++) {
            int   j  = __shfl_sync(0xFFFFFFFFu, myj,  p);
            float a0 = __shfl_sync(0xFFFFFFFFu, a4.x, p);
            float a1 = __shfl_sync(0xFFFFFFFFu, a4.y, p);
            float a2 = __shfl_sync(0xFFFFFFFFu, a4.z, p);
            float a3 = __shfl_sync(0xFFFFFFFFu, a4.w, p);

            uint4 u = __ldg((const uint4*)(g_vh + (size_t)j * 128) + lane);
            float2 f0 = __half22float2(*reinterpret_cast<__half2*>(&u.x));
            float2 f1 = __half22float2(*reinterpret_cast<__half2*>(&u.y));
            float2 f2 = __half22float2(*reinterpret_cast<__half2*>(&u.z));
            float2 f3 = __half22float2(*reinterpret_cast<__half2*>(&u.w));
            float2 r;
            r.x = a0 * f0.x + a1 * f1.x + a2 * f2.x + a3 * f3.x;
            r.y = a0 * f0.y + a1 * f1.y + a2 * f2.y + a3 * f3.y;
            __stcs(ob + p * 32, r);
        }
    } else {
        for (int p = 0; p < 8 && w + p < total; p++) {
            int   j  = __shfl_sync(0xFFFFFFFFu, myj,  p);
            float a0 = __shfl_sync(0xFFFFFFFFu, a4.x, p);
            float a1 = __shfl_sync(0xFFFFFFFFu, a4.y, p);
            float a2 = __shfl_sync(0xFFFFFFFFu, a4.z, p);
            float a3 = __shfl_sync(0xFFFFFFFFu, a4.w, p);

            uint4 u = __ldg((const uint4*)(g_vh + (size_t)j * 128) + lane);
            float2 f0 = __half22float2(*reinterpret_cast<__half2*>(&u.x));
            float2 f1 = __half22float2(*reinterpret_cast<__half2*>(&u.y));
            float2 f2 = __half22float2(*reinterpret_cast<__half2*>(&u.z));
            float2 f3 = __half22float2(*reinterpret_cast<__half2*>(&u.w));
            float2 r;
            r.x = a0 * f0.x + a1 * f1.x + a2 * f2.x + a3 * f3.x;
            r.y = a0 * f0.y + a1 * f1.y + a2 * f2.y + a3 * f3.y;
            __stcs((float2*)out + (size_t)(w + p) * 32 + lane, r);
        }
    }
}

// ---------------------------------------------------------------------------
extern "C" void kernel_launch(void* const* d_in, const int* in_sizes, int n_in,
                              void* d_out, int out_size)
{
    const float* x     = (const float*)d_in[0];
    const float* src   = (const float*)d_in[1];
    const int*   nidx  = (const int*)d_in[2];
    const float* Wt    = (const float*)d_in[3];
    const float* bt    = (const float*)d_in[4];
    const float* Ws    = (const float*)d_in[5];
    const float* bs    = (const float*)d_in[6];
    const float* W_lin = (const float*)d_in[7];
    const float* b_lin = (const float*)d_in[8];
    float* out = (float*)d_out;

    int N  = in_sizes[0] / CDIM;       // 50000
    int NK = in_sizes[2];              // N*K = 800000
    if (N > MAXN) N = MAXN;

    int tiles = (N + 63) / 64;         // 782

    // 1) fused v-table + logits (logits hides under FMA-bound vtable)
    k_tables<<<2 * tiles, 256>>>(x, src, Wt, bt, Ws, bs, W_lin, b_lin, N, tiles);

    // 2) fused softmax + gather + combine: 8 pairs per warp
    int gwarps = (NK + 7) / 8;
    k_gather<<<(gwarps + 7) / 8, 256>>>(nidx, out, NK);
}

// round 9
// speedup vs baseline: 4.4603x; 1.0932x over previous
#include <cuda_runtime.h>
#include <cuda_fp16.h>

// Problem constants (fixed by dataset)
#define MAXN 50000
#define CDIM 64
#define SDIM 4
#define ODIM 64
#define KNEI 16

// Scratch (static __device__ — allocation-free per harness rules)
// v-table fp16: g_vh[j*128 + q*4 + s] = half2 of outputs (2q, 2q+1) of matrix s.
__device__ __half2 g_vh[MAXN * 128];          // 25.6 MB — L2 resident
__device__ float   g_t[MAXN * SDIM];          // x[n]@Wt + bt
__device__ float   g_sl[MAXN * SDIM];         // src[j]@Ws + bs

// W_lin pre-split into mma B-fragment layout (hi/lo fp16 halves).
// half2 pair index p = (ks*256 + col)*4 + tig, holding {b0, b1} at p*2, p*2+1:
//   b0 = {W[k0][o], W[k0+1][o]},  k0 = ks*16 + 2*tig      (s = col>>6, o = col&63)
//   b1 = {W[k1][o], W[k1+1][o]},  k1 = ks*16 + 8 + 2*tig
__device__ __half2 g_Bhi[8192];
__device__ __half2 g_Blo[8192];

// ---------------------------------------------------------------------------
// Prep: split W_lin into fp16 hi/lo B-fragments. 8192 entries (half2 pairs x2).
// ---------------------------------------------------------------------------
__global__ void k_prep(const float* __restrict__ W_lin)
{
    int i = blockIdx.x * blockDim.x + threadIdx.x;   // 0..8191
    if (i >= 8192) return;
    int wh  = i & 1;
    int tig = (i >> 1) & 3;
    int col = (i >> 3) & 255;
    int ks  = i >> 11;

    int s = col >> 6, o = col & 63;
    int k = ks * 16 + wh * 8 + 2 * tig;

    float w0 = __ldg(W_lin + s * 4096 + k * 64 + o);
    float w1 = __ldg(W_lin + s * 4096 + (k + 1) * 64 + o);

    __half h0 = __float2half_rn(w0);
    __half h1 = __float2half_rn(w1);
    __half l0 = __float2half_rn(w0 - __half2float(h0));
    __half l1 = __float2half_rn(w1 - __half2float(h1));

    g_Bhi[i] = __halves2half2(h0, h1);
    g_Blo[i] = __halves2half2(l0, l1);
}

__device__ __forceinline__ void mma16816(float& c0, float& c1, float& c2, float& c3,
                                         unsigned a0, unsigned a1, unsigned a2, unsigned a3,
                                         unsigned b0, unsigned b1)
{
    asm volatile("mma.sync.aligned.m16n8k16.row.col.f32.f16.f16.f32 "
                 "{%0,%1,%2,%3}, {%4,%5,%6,%7}, {%8,%9}, {%0,%1,%2,%3};"
                 : "+f"(c0), "+f"(c1), "+f"(c2), "+f"(c3)
                 : "r"(a0), "r"(a1), "r"(a2), "r"(a3), "r"(b0), "r"(b1));
}

// ---------------------------------------------------------------------------
// Fused kernel: role-split grid.
//   blocks [0, vtBlocks)           : v-table GEMM via HMMA (fp16 hi/lo 3-pass)
//   blocks [vtBlocks, +vtBlocks)   : logits tables
// ---------------------------------------------------------------------------
__global__ void __launch_bounds__(256, 2) k_tables(const float* __restrict__ x,
                                                   const float* __restrict__ src,
                                                   const float* __restrict__ Wt,     // [64,4]
                                                   const float* __restrict__ bt,     // [4]
                                                   const float* __restrict__ Ws,     // [64,4]
                                                   const float* __restrict__ bs,     // [4]
                                                   const float* __restrict__ W_lin,  // unused here
                                                   const float* __restrict__ b_lin,  // [4,64]
                                                   int N, int vtBlocks)
{
    __shared__ __align__(16) char smraw[35328];
    int t = threadIdx.x;

    if ((int)blockIdx.x < vtBlocks) {
        // ================= v-table role (HMMA) =================
        __half2* AH = reinterpret_cast<__half2*>(smraw);            // [64][33] half2 (hi)
        __half2* AL = AH + 64 * 33;                                 // [64][33] half2 (lo)
        __half2* CS = reinterpret_cast<__half2*>(smraw);            // [64][132] half2 (reused)

        int lane = t & 31;
        int wid  = t >> 5;
        int g    = lane >> 2;       // groupID 0..7
        int tig  = lane & 3;        // thread-in-group 0..3
        int wm   = wid & 3;         // m-warp 0..3 -> rows m0..m0+15
        int wn   = wid >> 2;        // n-warp 0..1 -> cols wn*128..+127
        int m0   = wm * 16;
        int j0   = blockIdx.x * 64;

        // ---- stage src tile as fp16 hi/lo (rows 64 x 64 ch) ----
        {
            int row  = t >> 2;
            int quad = t & 3;
            int jg = j0 + row;
            const float4* srp = (const float4*)(src + (size_t)jg * CDIM) + quad * 4;
#pragma unroll
            for (int ii = 0; ii < 4; ii++) {
                float4 v = (jg < N) ? __ldg(srp + ii) : make_float4(0.f, 0.f, 0.f, 0.f);
                __half hx = __float2half_rn(v.x), hy = __float2half_rn(v.y);
                __half hz = __float2half_rn(v.z), hw = __float2half_rn(v.w);
                __half lx = __float2half_rn(v.x - __half2float(hx));
                __half ly = __float2half_rn(v.y - __half2float(hy));
                __half lz = __float2half_rn(v.z - __half2float(hz));
                __half lw = __float2half_rn(v.w - __half2float(hw));
                int cp = quad * 8 + ii * 2;          // colpair base
                AH[row * 33 + cp]     = __halves2half2(hx, hy);
                AH[row * 33 + cp + 1] = __halves2half2(hz, hw);
                AL[row * 33 + cp]     = __halves2half2(lx, ly);
                AL[row * 33 + cp + 1] = __halves2half2(lz, lw);
            }
        }
        __syncthreads();

        const unsigned* AHu = reinterpret_cast<const unsigned*>(AH);
        const unsigned* ALu = reinterpret_cast<const unsigned*>(AL);
        const uint2* BH = reinterpret_cast<const uint2*>(g_Bhi);
        const uint2* BL = reinterpret_cast<const uint2*>(g_Blo);

        float c[16][4];
#pragma unroll
        for (int nt = 0; nt < 16; nt++)
#pragma unroll
            for (int r = 0; r < 4; r++) c[nt][r] = 0.f;

        // A-hi fragments for all 4 k-steps
        unsigned Af[4][4];
#pragma unroll
        for (int ks = 0; ks < 4; ks++) {
            Af[ks][0] = AHu[(m0 + g) * 33 + ks * 8 + tig];
            Af[ks][1] = AHu[(m0 + g + 8) * 33 + ks * 8 + tig];
            Af[ks][2] = AHu[(m0 + g) * 33 + ks * 8 + tig + 4];
            Af[ks][3] = AHu[(m0 + g + 8) * 33 + ks * 8 + tig + 4];
        }

        // passes 1+2: Ahi x Bhi, Ahi x Blo
#pragma unroll
        for (int nt = 0; nt < 16; nt++) {
            int colg = wn * 128 + nt * 8 + g;
            uint2 bh[4];
#pragma unroll
            for (int ks = 0; ks < 4; ks++)
                bh[ks] = __ldg(BH + ((ks * 256 + colg) * 4 + tig));
#pragma unroll
            for (int ks = 0; ks < 4; ks++)
                mma16816(c[nt][0], c[nt][1], c[nt][2], c[nt][3],
                         Af[ks][0], Af[ks][1], Af[ks][2], Af[ks][3], bh[ks].x, bh[ks].y);
#pragma unroll
            for (int ks = 0; ks < 4; ks++)
                bh[ks] = __ldg(BL + ((ks * 256 + colg) * 4 + tig));
#pragma unroll
            for (int ks = 0; ks < 4; ks++)
                mma16816(c[nt][0], c[nt][1], c[nt][2], c[nt][3],
                         Af[ks][0], Af[ks][1], Af[ks][2], Af[ks][3], bh[ks].x, bh[ks].y);
        }

        // pass 3: Alo x Bhi
#pragma unroll
        for (int ks = 0; ks < 4; ks++) {
            Af[ks][0] = ALu[(m0 + g) * 33 + ks * 8 + tig];
            Af[ks][1] = ALu[(m0 + g + 8) * 33 + ks * 8 + tig];
            Af[ks][2] = ALu[(m0 + g) * 33 + ks * 8 + tig + 4];
            Af[ks][3] = ALu[(m0 + g + 8) * 33 + ks * 8 + tig + 4];
        }
#pragma unroll
        for (int nt = 0; nt < 16; nt++) {
            int colg = wn * 128 + nt * 8 + g;
            uint2 bh[4];
#pragma unroll
            for (int ks = 0; ks < 4; ks++)
                bh[ks] = __ldg(BH + ((ks * 256 + colg) * 4 + tig));
#pragma unroll
            for (int ks = 0; ks < 4; ks++)
                mma16816(c[nt][0], c[nt][1], c[nt][2], c[nt][3],
                         Af[ks][0], Af[ks][1], Af[ks][2], Af[ks][3], bh[ks].x, bh[ks].y);
        }
        __syncthreads();   // done reading A smem

        // ---- epilogue: scale+bias, fp16 pack, stage to smem C [64][132] ----
#pragma unroll
        for (int nt = 0; nt < 16; nt++) {
            int col0 = wn * 128 + nt * 8 + 2 * tig;
            int s = col0 >> 6, o = col0 & 63, q = o >> 1;
            float bb0 = __ldg(b_lin + s * 64 + o) * 0.25f;
            float bb1 = __ldg(b_lin + s * 64 + o + 1) * 0.25f;
            __half2 h0 = __floats2half2_rn(c[nt][0] * 0.25f + bb0, c[nt][1] * 0.25f + bb1);
            __half2 h1 = __floats2half2_rn(c[nt][2] * 0.25f + bb0, c[nt][3] * 0.25f + bb1);
            CS[(m0 + g) * 132 + s * 32 + q]     = h0;
            CS[(m0 + g + 8) * 132 + s * 32 + q] = h1;
        }
        __syncthreads();

        // ---- coalesced copy smem C -> g_vh (uint4 per (j, pair q)) ----
        const unsigned* cu = reinterpret_cast<const unsigned*>(CS);
        for (int it = t; it < 2048; it += 256) {
            int jloc = it >> 5, q = it & 31;
            int j = j0 + jloc;
            if (j < N) {
                uint4 u;
                u.x = cu[jloc * 132 + q];
                u.y = cu[jloc * 132 + 32 + q];
                u.z = cu[jloc * 132 + 64 + q];
                u.w = cu[jloc * 132 + 96 + q];
                ((uint4*)(g_vh + (size_t)j * 128))[q] = u;
            }
        }
    } else {
        // ================= logits role =================
        float (*xs)[65]  = reinterpret_cast<float (*)[65]>(smraw);
        float (*ssl)[65] = reinterpret_cast<float (*)[65]>(smraw + 16640);
        float (*wts)[4]  = reinterpret_cast<float (*)[4]>(smraw + 33280);
        float (*wss)[4]  = reinterpret_cast<float (*)[4]>(smraw + 34304);

        int nb = (blockIdx.x - vtBlocks) * 64;

        wts[t >> 2][t & 3] = __ldg(Wt + t);
        wss[t >> 2][t & 3] = __ldg(Ws + t);

        for (int i = t; i < 64 * 16; i += 256) {
            int row = i >> 4, c4 = i & 15;
            int node = nb + row;
            float4 xv = make_float4(0.f, 0.f, 0.f, 0.f);
            float4 sv = make_float4(0.f, 0.f, 0.f, 0.f);
            if (node < N) {
                xv = __ldg((const float4*)x + node * 16 + c4);
                sv = __ldg((const float4*)src + node * 16 + c4);
            }
            xs[row][c4 * 4 + 0] = xv.x;  xs[row][c4 * 4 + 1] = xv.y;
            xs[row][c4 * 4 + 2] = xv.z;  xs[row][c4 * 4 + 3] = xv.w;
            ssl[row][c4 * 4 + 0] = sv.x; ssl[row][c4 * 4 + 1] = sv.y;
            ssl[row][c4 * 4 + 2] = sv.z; ssl[row][c4 * 4 + 3] = sv.w;
        }
        __syncthreads();

        int node = t >> 2;
        int s    = t & 3;
        float at  = __ldg(bt + s);
        float as_ = __ldg(bs + s);
#pragma unroll
        for (int c = 0; c < CDIM; c++) {
            at  = fmaf(xs[node][c], wts[c][s], at);
            as_ = fmaf(ssl[node][c], wss[c][s], as_);
        }
        int gn = nb + node;
        if (gn < N) {
            g_t[gn * 4 + s]  = at;
            g_sl[gn * 4 + s] = as_;
        }
    }
}

// ---------------------------------------------------------------------------
// Fused softmax + gather + combine, 8 pairs per warp (unchanged from R7).
// ---------------------------------------------------------------------------
__global__ void __launch_bounds__(256) k_gather(const int* __restrict__ idx,
                                                float* __restrict__ out,
                                                int total /* N*K */)
{
    int lane = threadIdx.x & 31;
    int gw   = (blockIdx.x * blockDim.x + threadIdx.x) >> 5;
    int w    = gw * 8;
    if (w >= total) return;

    int n = w >> 4;                         // same node for all 8 pairs
    float4 tv = __ldg((const float4*)g_t + n);   // uniform

    int   myj = 0;
    float4 a4 = make_float4(0.f, 0.f, 0.f, 0.f);
    if (lane < 8) {
        int wi = w + lane;
        if (wi < total) {
            myj = __ldg(idx + wi);
            float4 sv = __ldg((const float4*)g_sl + myj);
            float l0 = tv.x + sv.x, l1 = tv.y + sv.y;
            float l2 = tv.z + sv.z, l3 = tv.w + sv.w;
            float m = fmaxf(fmaxf(l0, l1), fmaxf(l2, l3));
            float e0 = __expf(l0 - m), e1 = __expf(l1 - m);
            float e2 = __expf(l2 - m), e3 = __expf(l3 - m);
            float inv = 1.0f / (e0 + e1 + e2 + e3);
            a4 = make_float4(e0 * inv, e1 * inv, e2 * inv, e3 * inv);
        }
    }

    if (w + 7 < total) {
        float2* ob = (float2*)out + (size_t)w * 32 + lane;
#pragma unroll
        for (int p = 0; p < 8; p++) {
            int   j  = __shfl_sync(0xFFFFFFFFu, myj,  p);
            float a0 = __shfl_sync(0xFFFFFFFFu, a4.x, p);
            float a1 = __shfl_sync(0xFFFFFFFFu, a4.y, p);
            float a2 = __shfl_sync(0xFFFFFFFFu, a4.z, p);
            float a3 = __shfl_sync(0xFFFFFFFFu, a4.w, p);

            uint4 u = __ldg((const uint4*)(g_vh + (size_t)j * 128) + lane);
            float2 f0 = __half22float2(*reinterpret_cast<__half2*>(&u.x));
            float2 f1 = __half22float2(*reinterpret_cast<__half2*>(&u.y));
            float2 f2 = __half22float2(*reinterpret_cast<__half2*>(&u.z));
            float2 f3 = __half22float2(*reinterpret_cast<__half2*>(&u.w));
            float2 r;
            r.x = a0 * f0.x + a1 * f1.x + a2 * f2.x + a3 * f3.x;
            r.y = a0 * f0.y + a1 * f1.y + a2 * f2.y + a3 * f3.y;
            __stcs(ob + p * 32, r);
        }
    } else {
        for (int p = 0; p < 8 && w + p < total; p++) {
            int   j  = __shfl_sync(0xFFFFFFFFu, myj,  p);
            float a0 = __shfl_sync(0xFFFFFFFFu, a4.x, p);
            float a1 = __shfl_sync(0xFFFFFFFFu, a4.y, p);
            float a2 = __shfl_sync(0xFFFFFFFFu, a4.z, p);
            float a3 = __shfl_sync(0xFFFFFFFFu, a4.w, p);

            uint4 u = __ldg((const uint4*)(g_vh + (size_t)j * 128) + lane);
            float2 f0 = __half22float2(*reinterpret_cast<__half2*>(&u.x));
            float2 f1 = __half22float2(*reinterpret_cast<__half2*>(&u.y));
            float2 f2 = __half22float2(*reinterpret_cast<__half2*>(&u.z));
            float2 f3 = __half22float2(*reinterpret_cast<__half2*>(&u.w));
            float2 r;
            r.x = a0 * f0.x + a1 * f1.x + a2 * f2.x + a3 * f3.x;
            r.y = a0 * f0.y + a1 * f1.y + a2 * f2.y + a3 * f3.y;
            __stcs((float2*)out + (size_t)(w + p) * 32 + lane, r);
        }
    }
}

// ---------------------------------------------------------------------------
extern "C" void kernel_launch(void* const* d_in, const int* in_sizes, int n_in,
                              void* d_out, int out_size)
{
    const float* x     = (const float*)d_in[0];
    const float* src   = (const float*)d_in[1];
    const int*   nidx  = (const int*)d_in[2];
    const float* Wt    = (const float*)d_in[3];
    const float* bt    = (const float*)d_in[4];
    const float* Ws    = (const float*)d_in[5];
    const float* bs    = (const float*)d_in[6];
    const float* W_lin = (const float*)d_in[7];
    const float* b_lin = (const float*)d_in[8];
    float* out = (float*)d_out;

    int N  = in_sizes[0] / CDIM;       // 50000
    int NK = in_sizes[2];              // N*K = 800000
    if (N > MAXN) N = MAXN;

    int tiles = (N + 63) / 64;         // 782

    // 0) split W into fp16 hi/lo mma fragments
    k_prep<<<32, 256>>>(W_lin);

    // 1) fused v-table (HMMA) + logits
    k_tables<<<2 * tiles, 256>>>(x, src, Wt, bt, Ws, bs, W_lin, b_lin, N, tiles);

    // 2) fused softmax + gather + combine: 8 pairs per warp
    int gwarps = (NK + 7) / 8;
    k_gather<<<(gwarps + 7) / 8, 256>>>(nidx, out, NK);
}

// round 10
// speedup vs baseline: 4.5422x; 1.0184x over previous
#include <cuda_runtime.h>
#include <cuda_fp16.h>

// Problem constants (fixed by dataset)
#define MAXN 50000
#define CDIM 64
#define SDIM 4
#define ODIM 64
#define KNEI 16

// Scratch (static __device__ — allocation-free per harness rules)
// v-table fp16: g_vh[j*128 + q*4 + s] = half2 of outputs (2q, 2q+1) of matrix s.
__device__ __half2 g_vh[MAXN * 128];          // 25.6 MB — L2 resident
__device__ float   g_t[MAXN * SDIM];          // x[n]@Wt + bt
__device__ float   g_sl[MAXN * SDIM];         // src[j]@Ws + bs

// W_lin pre-split into mma B-fragment layout (hi/lo fp16 halves).
__device__ __half2 g_Bhi[8192];
__device__ __half2 g_Blo[8192];
// Wt / Ws fragments (N padded 4->8), 256 half2 each per precision
__device__ __half2 g_WtHi[256];
__device__ __half2 g_WtLo[256];
__device__ __half2 g_WsHi[256];
__device__ __half2 g_WsLo[256];

// ---------------------------------------------------------------------------
// Prep: split W_lin (+ Wt, Ws) into fp16 hi/lo B-fragments.
// ---------------------------------------------------------------------------
__global__ void k_prep(const float* __restrict__ W_lin,
                       const float* __restrict__ Wt,   // [64,4]
                       const float* __restrict__ Ws)   // [64,4]
{
    int i = blockIdx.x * blockDim.x + threadIdx.x;
    if (i < 8192) {
        int wh  = i & 1;
        int tig = (i >> 1) & 3;
        int col = (i >> 3) & 255;
        int ks  = i >> 11;
        int s = col >> 6, o = col & 63;
        int k = ks * 16 + wh * 8 + 2 * tig;

        float w0 = __ldg(W_lin + s * 4096 + k * 64 + o);
        float w1 = __ldg(W_lin + s * 4096 + (k + 1) * 64 + o);
        __half h0 = __float2half_rn(w0), h1 = __float2half_rn(w1);
        __half l0 = __float2half_rn(w0 - __half2float(h0));
        __half l1 = __float2half_rn(w1 - __half2float(h1));
        g_Bhi[i] = __halves2half2(h0, h1);
        g_Blo[i] = __halves2half2(l0, l1);
    } else if (i < 8704) {
        int idx = i - 8192;
        int mat = idx >> 8;            // 0 = Wt, 1 = Ws
        int e   = idx & 255;
        int wh = e & 1, tig = (e >> 1) & 3, col = (e >> 3) & 7, ks = (e >> 6) & 3;
        int k = ks * 16 + wh * 8 + 2 * tig;
        const float* W = mat ? Ws : Wt;
        float w0 = 0.f, w1 = 0.f;
        if (col < 4) {
            w0 = __ldg(W + k * 4 + col);
            w1 = __ldg(W + (k + 1) * 4 + col);
        }
        __half h0 = __float2half_rn(w0), h1 = __float2half_rn(w1);
        __half l0 = __float2half_rn(w0 - __half2float(h0));
        __half l1 = __float2half_rn(w1 - __half2float(h1));
        if (mat) { g_WsHi[e] = __halves2half2(h0, h1); g_WsLo[e] = __halves2half2(l0, l1); }
        else     { g_WtHi[e] = __halves2half2(h0, h1); g_WtLo[e] = __halves2half2(l0, l1); }
    }
}

__device__ __forceinline__ void mma16816(float& c0, float& c1, float& c2, float& c3,
                                         unsigned a0, unsigned a1, unsigned a2, unsigned a3,
                                         unsigned b0, unsigned b1)
{
    asm volatile("mma.sync.aligned.m16n8k16.row.col.f32.f16.f16.f32 "
                 "{%0,%1,%2,%3}, {%4,%5,%6,%7}, {%8,%9}, {%0,%1,%2,%3};"
                 : "+f"(c0), "+f"(c1), "+f"(c2), "+f"(c3)
                 : "r"(a0), "r"(a1), "r"(a2), "r"(a3), "r"(b0), "r"(b1));
}

// ---------------------------------------------------------------------------
// Fused kernel: each block handles 64 rows — v-table GEMM (HMMA hi/lo 3-pass)
// AND both logits GEMMs (t, sl) on the tensor pipe. No scalar-GEMM role left.
// ---------------------------------------------------------------------------
__global__ void __launch_bounds__(256, 2) k_tables(const float* __restrict__ x,
                                                   const float* __restrict__ src,
                                                   const float* __restrict__ bt,     // [4]
                                                   const float* __restrict__ bs,     // [4]
                                                   const float* __restrict__ b_lin,  // [4,64]
                                                   int N)
{
    __shared__ __align__(16) char smraw[33856];
    __half2* AH = reinterpret_cast<__half2*>(smraw);            // src hi [64][33]
    __half2* AL = AH + 2112;                                    // src lo
    __half2* XH = AH + 4224;                                    // x hi
    __half2* XL = AH + 6336;                                    // x lo
    __half2* CS = reinterpret_cast<__half2*>(smraw);            // epilogue reuse [64][132]

    int t    = threadIdx.x;
    int lane = t & 31;
    int wid  = t >> 5;
    int g    = lane >> 2;       // groupID 0..7
    int tig  = lane & 3;        // thread-in-group 0..3
    int wm   = wid & 3;         // m-warp 0..3 -> rows m0..m0+15
    int wn   = wid >> 2;        // n-warp 0..1 -> vtable cols wn*128..+127
    int m0   = wm * 16;
    int j0   = blockIdx.x * 64;

    // ---- stage src and x tiles as fp16 hi/lo ----
    {
        int row  = t >> 2;
        int quad = t & 3;
        int jg = j0 + row;
        const float4* srp = (const float4*)(src + (size_t)jg * CDIM) + quad * 4;
        const float4* xrp = (const float4*)(x   + (size_t)jg * CDIM) + quad * 4;
#pragma unroll
        for (int ii = 0; ii < 4; ii++) {
            float4 v = (jg < N) ? __ldg(srp + ii) : make_float4(0.f, 0.f, 0.f, 0.f);
            float4 u = (jg < N) ? __ldg(xrp + ii) : make_float4(0.f, 0.f, 0.f, 0.f);
            int cp = quad * 8 + ii * 2;
            {
                __half hx = __float2half_rn(v.x), hy = __float2half_rn(v.y);
                __half hz = __float2half_rn(v.z), hw = __float2half_rn(v.w);
                AH[row * 33 + cp]     = __halves2half2(hx, hy);
                AH[row * 33 + cp + 1] = __halves2half2(hz, hw);
                AL[row * 33 + cp]     = __halves2half2(__float2half_rn(v.x - __half2float(hx)),
                                                       __float2half_rn(v.y - __half2float(hy)));
                AL[row * 33 + cp + 1] = __halves2half2(__float2half_rn(v.z - __half2float(hz)),
                                                       __float2half_rn(v.w - __half2float(hw)));
            }
            {
                __half hx = __float2half_rn(u.x), hy = __float2half_rn(u.y);
                __half hz = __float2half_rn(u.z), hw = __float2half_rn(u.w);
                XH[row * 33 + cp]     = __halves2half2(hx, hy);
                XH[row * 33 + cp + 1] = __halves2half2(hz, hw);
                XL[row * 33 + cp]     = __halves2half2(__float2half_rn(u.x - __half2float(hx)),
                                                       __float2half_rn(u.y - __half2float(hy)));
                XL[row * 33 + cp + 1] = __halves2half2(__float2half_rn(u.z - __half2float(hz)),
                                                       __float2half_rn(u.w - __half2float(hw)));
            }
        }
    }
    __syncthreads();

    const unsigned* AHu = reinterpret_cast<const unsigned*>(AH);
    const unsigned* ALu = reinterpret_cast<const unsigned*>(AL);
    const unsigned* XHu = reinterpret_cast<const unsigned*>(XH);
    const unsigned* XLu = reinterpret_cast<const unsigned*>(XL);
    const uint2* BH = reinterpret_cast<const uint2*>(g_Bhi);
    const uint2* BL = reinterpret_cast<const uint2*>(g_Blo);

    float c[16][4];
#pragma unroll
    for (int nt = 0; nt < 16; nt++)
#pragma unroll
        for (int r = 0; r < 4; r++) c[nt][r] = 0.f;

    unsigned Af[4][4];
#pragma unroll
    for (int ks = 0; ks < 4; ks++) {
        Af[ks][0] = AHu[(m0 + g) * 33 + ks * 8 + tig];
        Af[ks][1] = AHu[(m0 + g + 8) * 33 + ks * 8 + tig];
        Af[ks][2] = AHu[(m0 + g) * 33 + ks * 8 + tig + 4];
        Af[ks][3] = AHu[(m0 + g + 8) * 33 + ks * 8 + tig + 4];
    }

    // vtable passes 1+2: Ahi x Bhi, Ahi x Blo
#pragma unroll
    for (int nt = 0; nt < 16; nt++) {
        int colg = wn * 128 + nt * 8 + g;
        uint2 bh[4];
#pragma unroll
        for (int ks = 0; ks < 4; ks++)
            bh[ks] = __ldg(BH + ((ks * 256 + colg) * 4 + tig));
#pragma unroll
        for (int ks = 0; ks < 4; ks++)
            mma16816(c[nt][0], c[nt][1], c[nt][2], c[nt][3],
                     Af[ks][0], Af[ks][1], Af[ks][2], Af[ks][3], bh[ks].x, bh[ks].y);
#pragma unroll
        for (int ks = 0; ks < 4; ks++)
            bh[ks] = __ldg(BL + ((ks * 256 + colg) * 4 + tig));
#pragma unroll
        for (int ks = 0; ks < 4; ks++)
            mma16816(c[nt][0], c[nt][1], c[nt][2], c[nt][3],
                     Af[ks][0], Af[ks][1], Af[ks][2], Af[ks][3], bh[ks].x, bh[ks].y);
    }

    // vtable pass 3: Alo x Bhi
#pragma unroll
    for (int ks = 0; ks < 4; ks++) {
        Af[ks][0] = ALu[(m0 + g) * 33 + ks * 8 + tig];
        Af[ks][1] = ALu[(m0 + g + 8) * 33 + ks * 8 + tig];
        Af[ks][2] = ALu[(m0 + g) * 33 + ks * 8 + tig + 4];
        Af[ks][3] = ALu[(m0 + g + 8) * 33 + ks * 8 + tig + 4];
    }
#pragma unroll
    for (int nt = 0; nt < 16; nt++) {
        int colg = wn * 128 + nt * 8 + g;
        uint2 bh[4];
#pragma unroll
        for (int ks = 0; ks < 4; ks++)
            bh[ks] = __ldg(BH + ((ks * 256 + colg) * 4 + tig));
#pragma unroll
        for (int ks = 0; ks < 4; ks++)
            mma16816(c[nt][0], c[nt][1], c[nt][2], c[nt][3],
                     Af[ks][0], Af[ks][1], Af[ks][2], Af[ks][3], bh[ks].x, bh[ks].y);
    }

    // ---- logits GEMM: wn=0 -> t = x@Wt (+bt); wn=1 -> sl = src@Ws (+bs) ----
    {
        const unsigned* MHu = (wn == 0) ? XHu : AHu;
        const unsigned* MLu = (wn == 0) ? XLu : ALu;
        const uint2* LBH = (wn == 0) ? (const uint2*)g_WtHi : (const uint2*)g_WsHi;
        const uint2* LBL = (wn == 0) ? (const uint2*)g_WtLo : (const uint2*)g_WsLo;

        float cl0 = 0.f, cl1 = 0.f, cl2 = 0.f, cl3 = 0.f;
        unsigned Lf[4][4];
#pragma unroll
        for (int ks = 0; ks < 4; ks++) {
            Lf[ks][0] = MHu[(m0 + g) * 33 + ks * 8 + tig];
            Lf[ks][1] = MHu[(m0 + g + 8) * 33 + ks * 8 + tig];
            Lf[ks][2] = MHu[(m0 + g) * 33 + ks * 8 + tig + 4];
            Lf[ks][3] = MHu[(m0 + g + 8) * 33 + ks * 8 + tig + 4];
        }
#pragma unroll
        for (int ks = 0; ks < 4; ks++) {
            uint2 b = __ldg(LBH + (ks * 32 + g * 4 + tig));
            mma16816(cl0, cl1, cl2, cl3, Lf[ks][0], Lf[ks][1], Lf[ks][2], Lf[ks][3], b.x, b.y);
        }
#pragma unroll
        for (int ks = 0; ks < 4; ks++) {
            uint2 b = __ldg(LBL + (ks * 32 + g * 4 + tig));
            mma16816(cl0, cl1, cl2, cl3, Lf[ks][0], Lf[ks][1], Lf[ks][2], Lf[ks][3], b.x, b.y);
        }
#pragma unroll
        for (int ks = 0; ks < 4; ks++) {
            Lf[ks][0] = MLu[(m0 + g) * 33 + ks * 8 + tig];
            Lf[ks][1] = MLu[(m0 + g + 8) * 33 + ks * 8 + tig];
            Lf[ks][2] = MLu[(m0 + g) * 33 + ks * 8 + tig + 4];
            Lf[ks][3] = MLu[(m0 + g + 8) * 33 + ks * 8 + tig + 4];
        }
#pragma unroll
        for (int ks = 0; ks < 4; ks++) {
            uint2 b = __ldg(LBH + (ks * 32 + g * 4 + tig));
            mma16816(cl0, cl1, cl2, cl3, Lf[ks][0], Lf[ks][1], Lf[ks][2], Lf[ks][3], b.x, b.y);
        }

        if (tig < 2) {   // cols 2tig, 2tig+1 are the real s-values (0..3)
            const float* bv = (wn == 0) ? bt : bs;
            float bias0 = __ldg(bv + 2 * tig);
            float bias1 = __ldg(bv + 2 * tig + 1);
            float* dst = (wn == 0) ? g_t : g_sl;
            int row0 = j0 + m0 + g, row1 = row0 + 8;
            if (row0 < N)
                *(float2*)(dst + row0 * 4 + 2 * tig) = make_float2(cl0 + bias0, cl1 + bias1);
            if (row1 < N)
                *(float2*)(dst + row1 * 4 + 2 * tig) = make_float2(cl2 + bias0, cl3 + bias1);
        }
    }
    __syncthreads();   // done reading A/X smem

    // ---- vtable epilogue: scale+bias, fp16 pack, stage to smem C [64][132] ----
#pragma unroll
    for (int nt = 0; nt < 16; nt++) {
        int col0 = wn * 128 + nt * 8 + 2 * tig;
        int s = col0 >> 6, o = col0 & 63, q = o >> 1;
        float bb0 = __ldg(b_lin + s * 64 + o) * 0.25f;
        float bb1 = __ldg(b_lin + s * 64 + o + 1) * 0.25f;
        __half2 h0 = __floats2half2_rn(c[nt][0] * 0.25f + bb0, c[nt][1] * 0.25f + bb1);
        __half2 h1 = __floats2half2_rn(c[nt][2] * 0.25f + bb0, c[nt][3] * 0.25f + bb1);
        CS[(m0 + g) * 132 + s * 32 + q]     = h0;
        CS[(m0 + g + 8) * 132 + s * 32 + q] = h1;
    }
    __syncthreads();

    // ---- coalesced copy smem C -> g_vh (uint4 per (j, pair q)) ----
    const unsigned* cu = reinterpret_cast<const unsigned*>(CS);
    for (int it = t; it < 2048; it += 256) {
        int jloc = it >> 5, q = it & 31;
        int j = j0 + jloc;
        if (j < N) {
            uint4 u;
            u.x = cu[jloc * 132 + q];
            u.y = cu[jloc * 132 + 32 + q];
            u.z = cu[jloc * 132 + 64 + q];
            u.w = cu[jloc * 132 + 96 + q];
            ((uint4*)(g_vh + (size_t)j * 128))[q] = u;
        }
    }
}

// ---------------------------------------------------------------------------
// Fused softmax + gather + combine, 8 pairs per warp (unchanged from R7).
// ---------------------------------------------------------------------------
__global__ void __launch_bounds__(256) k_gather(const int* __restrict__ idx,
                                                float* __restrict__ out,
                                                int total /* N*K */)
{
    int lane = threadIdx.x & 31;
    int gw   = (blockIdx.x * blockDim.x + threadIdx.x) >> 5;
    int w    = gw * 8;
    if (w >= total) return;

    int n = w >> 4;
    float4 tv = __ldg((const float4*)g_t + n);

    int   myj = 0;
    float4 a4 = make_float4(0.f, 0.f, 0.f, 0.f);
    if (lane < 8) {
        int wi = w + lane;
        if (wi < total) {
            myj = __ldg(idx + wi);
            float4 sv = __ldg((const float4*)g_sl + myj);
            float l0 = tv.x + sv.x, l1 = tv.y + sv.y;
            float l2 = tv.z + sv.z, l3 = tv.w + sv.w;
            float m = fmaxf(fmaxf(l0, l1), fmaxf(l2, l3));
            float e0 = __expf(l0 - m), e1 = __expf(l1 - m);
            float e2 = __expf(l2 - m), e3 = __expf(l3 - m);
            float inv = 1.0f / (e0 + e1 + e2 + e3);
            a4 = make_float4(e0 * inv, e1 * inv, e2 * inv, e3 * inv);
        }
    }

    if (w + 7 < total) {
        float2* ob = (float2*)out + (size_t)w * 32 + lane;
#pragma unroll
        for (int p = 0; p < 8; p++) {
            int   j  = __shfl_sync(0xFFFFFFFFu, myj,  p);
            float a0 = __shfl_sync(0xFFFFFFFFu, a4.x, p);
            float a1 = __shfl_sync(0xFFFFFFFFu, a4.y, p);
            float a2 = __shfl_sync(0xFFFFFFFFu, a4.z, p);
            float a3 = __shfl_sync(0xFFFFFFFFu, a4.w, p);

            uint4 u = __ldg((const uint4*)(g_vh + (size_t)j * 128) + lane);
            float2 f0 = __half22float2(*reinterpret_cast<__half2*>(&u.x));
            float2 f1 = __half22float2(*reinterpret_cast<__half2*>(&u.y));
            float2 f2 = __half22float2(*reinterpret_cast<__half2*>(&u.z));
            float2 f3 = __half22float2(*reinterpret_cast<__half2*>(&u.w));
            float2 r;
            r.x = a0 * f0.x + a1 * f1.x + a2 * f2.x + a3 * f3.x;
            r.y = a0 * f0.y + a1 * f1.y + a2 * f2.y + a3 * f3.y;
            __stcs(ob + p * 32, r);
        }
    } else {
        for (int p = 0; p < 8 && w + p < total; p++) {
            int   j  = __shfl_sync(0xFFFFFFFFu, myj,  p);
            float a0 = __shfl_sync(0xFFFFFFFFu, a4.x, p);
            float a1 = __shfl_sync(0xFFFFFFFFu, a4.y, p);
            float a2 = __shfl_sync(0xFFFFFFFFu, a4.z, p);
            float a3 = __shfl_sync(0xFFFFFFFFu, a4.w, p);

            uint4 u = __ldg((const uint4*)(g_vh + (size_t)j * 128) + lane);
            float2 f0 = __half22float2(*reinterpret_cast<__half2*>(&u.x));
            float2 f1 = __half22float2(*reinterpret_cast<__half2*>(&u.y));
            float2 f2 = __half22float2(*reinterpret_cast<__half2*>(&u.z));
            float2 f3 = __half22float2(*reinterpret_cast<__half2*>(&u.w));
            float2 r;
            r.x = a0 * f0.x + a1 * f1.x + a2 * f2.x + a3 * f3.x;
            r.y = a0 * f0.y + a1 * f1.y + a2 * f2.y + a3 * f3.y;
            __stcs((float2*)out + (size_t)(w + p) * 32 + lane, r);
        }
    }
}

// ---------------------------------------------------------------------------
extern "C" void kernel_launch(void* const* d_in, const int* in_sizes, int n_in,
                              void* d_out, int out_size)
{
    const float* x     = (const float*)d_in[0];
    const float* src   = (const float*)d_in[1];
    const int*   nidx  = (const int*)d_in[2];
    const float* Wt    = (const float*)d_in[3];
    const float* bt    = (const float*)d_in[4];
    const float* Ws    = (const float*)d_in[5];
    const float* bs    = (const float*)d_in[6];
    const float* W_lin = (const float*)d_in[7];
    const float* b_lin = (const float*)d_in[8];
    float* out = (float*)d_out;

    int N  = in_sizes[0] / CDIM;       // 50000
    int NK = in_sizes[2];              // N*K = 800000
    if (N > MAXN) N = MAXN;

    int tiles = (N + 63) / 64;         // 782

    // 0) split W_lin, Wt, Ws into fp16 hi/lo mma fragments
    k_prep<<<34, 256>>>(W_lin, Wt, Ws);

    // 1) fused v-table + logits (all on tensor pipe)
    k_tables<<<tiles, 256>>>(x, src, bt, bs, b_lin, N);

    // 2) fused softmax + gather + combine: 8 pairs per warp
    int gwarps = (NK + 7) / 8;
    k_gather<<<(gwarps + 7) / 8, 256>>>(nidx, out, NK);
}